// round 1
// baseline (speedup 1.0000x reference)
#include <cuda_runtime.h>
#include <math.h>

#define NTOK  16384
#define BATCH 8
#define SEQ   2048
#define DM    256
#define DI    512
#define DS    16

// ---------------- scratch (allocation-free: __device__ globals) ----------------
__device__ float g_ln[NTOK * DM];        // layernorm output
__device__ float g_xz[NTOK * 2 * DI];    // in_proj output (u | z)
__device__ float g_u[NTOK * DI];         // conv+silu output
__device__ float g_xdbl[NTOK * 48];      // x_proj output (dt_r | B | C)
__device__ float g_dt[NTOK * DI];        // softplus(dt)
__device__ float g_y[NTOK * DI];         // scan output, gated

__device__ __forceinline__ float sigmoidf_(float v) { return 1.f / (1.f + __expf(-v)); }

// ---------------- layernorm: one warp per token (256 feats, 8/lane) ------------
__global__ void ln_kernel(const float* __restrict__ x,
                          const float* __restrict__ g,
                          const float* __restrict__ b) {
    int warp = threadIdx.x >> 5, lane = threadIdx.x & 31;
    int tok = blockIdx.x * 8 + warp;
    const float* row = x + (size_t)tok * DM;
    float v[8];
    float s = 0.f, s2 = 0.f;
#pragma unroll
    for (int i = 0; i < 8; i++) {
        v[i] = row[lane + i * 32];
        s += v[i];
        s2 += v[i] * v[i];
    }
#pragma unroll
    for (int o = 16; o; o >>= 1) {
        s  += __shfl_xor_sync(0xffffffffu, s, o);
        s2 += __shfl_xor_sync(0xffffffffu, s2, o);
    }
    float m   = s * (1.f / DM);
    float var = s2 * (1.f / DM) - m * m;
    float inv = rsqrtf(var + 1e-5f);
    float* o = g_ln + (size_t)tok * DM;
#pragma unroll
    for (int i = 0; i < 8; i++) {
        int c = lane + i * 32;
        o[c] = (v[i] - m) * inv * g[c] + b[c];
    }
}

// ---------------- generic tiled GEMM: C[M,N] = A[M,K] * W[N,K]^T ----------------
// EPI: 0 = plain store, 1 = res + ls[n]*acc, 2 = softplus(acc + bias[n])
template <int BM, int BN, int BK, int TM, int TN, int EPI>
__global__ __launch_bounds__((BM / TM) * (BN / TN))
void gemm_tn(const float* __restrict__ A, int lda,
             const float* __restrict__ W,
             float* __restrict__ C,
             int N, int K,
             const float* __restrict__ res,
             const float* __restrict__ v1) {
    constexpr int TX = BN / TN, TY = BM / TM, NT = TX * TY;
    __shared__ float As[BK][BM + 4];
    __shared__ float Ws[BK][BN + 4];
    const int tid = threadIdx.x;
    const int tx = tid % TX, ty = tid / TX;
    const int m0 = blockIdx.y * BM, n0 = blockIdx.x * BN;

    float acc[TM][TN];
#pragma unroll
    for (int i = 0; i < TM; i++)
#pragma unroll
        for (int j = 0; j < TN; j++) acc[i][j] = 0.f;

    for (int k0 = 0; k0 < K; k0 += BK) {
#pragma unroll
        for (int t = 0; t < (BM * BK) / NT; t++) {
            int idx = tid + t * NT;
            int i = idx / BK, k = idx % BK;
            As[k][i] = A[(size_t)(m0 + i) * lda + k0 + k];
        }
#pragma unroll
        for (int t = 0; t < (BN * BK) / NT; t++) {
            int idx = tid + t * NT;
            int i = idx / BK, k = idx % BK;
            Ws[k][i] = W[(size_t)(n0 + i) * K + k0 + k];
        }
        __syncthreads();
#pragma unroll
        for (int kk = 0; kk < BK; kk++) {
            float a[TM], w[TN];
#pragma unroll
            for (int i = 0; i < TM; i++) a[i] = As[kk][ty * TM + i];
#pragma unroll
            for (int j = 0; j < TN; j++) w[j] = Ws[kk][tx * TN + j];
#pragma unroll
            for (int i = 0; i < TM; i++)
#pragma unroll
                for (int j = 0; j < TN; j++) acc[i][j] = fmaf(a[i], w[j], acc[i][j]);
        }
        __syncthreads();
    }

#pragma unroll
    for (int i = 0; i < TM; i++) {
        int m = m0 + ty * TM + i;
#pragma unroll
        for (int j = 0; j < TN; j++) {
            int n = n0 + tx * TN + j;
            float v = acc[i][j];
            if (EPI == 1) {
                v = res[(size_t)m * N + n] + v1[n] * v;
            } else if (EPI == 2) {
                v += v1[n];
                v = (v > 20.f) ? v : log1pf(__expf(v));  // softplus
            }
            C[(size_t)m * N + n] = v;
        }
    }
}

// ---------------- causal depthwise conv(4) + bias + SiLU ------------------------
__global__ void conv_silu_kernel(const float* __restrict__ cw,
                                 const float* __restrict__ cb) {
    int idx = blockIdx.x * blockDim.x + threadIdx.x;  // over NTOK*DI
    int d = idx & (DI - 1);
    int n = idx >> 9;         // token index (b*SEQ + l)
    int l = n & (SEQ - 1);
    float acc = cb[d];
    const float* w = cw + d * 4;
#pragma unroll
    for (int j = 0; j < 4; j++) {
        int ll = l - 3 + j;
        if (ll >= 0) acc = fmaf(w[j], g_xz[(size_t)(n - 3 + j) * (2 * DI) + d], acc);
    }
    g_u[idx] = acc * sigmoidf_(acc);
}

// ---------------- selective scan: 16 lanes per (b,d) channel --------------------
// block = 256 threads = 16 channels (same batch b). Sequential over L.
__global__ void scan_kernel(const float* __restrict__ A_log,
                            const float* __restrict__ Dp) {
    int tid = threadIdx.x;
    int half = tid >> 4;              // channel within block (0..15)
    int s = tid & 15;                 // state index
    int b = blockIdx.x >> 5;          // 32 blocks per batch (512/16)
    int d = ((blockIdx.x & 31) << 4) + half;

    float As = -__expf(A_log[d * DS + s]);
    float Dv = Dp[d];
    float h = 0.f;
    size_t base = (size_t)b * SEQ;

    for (int l = 0; l < SEQ; l++) {
        size_t n = base + l;
        float r  = g_dt[n * DI + d];            // broadcast within 16-lane group
        float uu = g_u[n * DI + d];
        float Bv = g_xdbl[n * 48 + 16 + s];
        float Cv = g_xdbl[n * 48 + 32 + s];
        float dA = __expf(r * As);
        h = fmaf(dA, h, (r * uu) * Bv);
        float p = h * Cv;
        p += __shfl_xor_sync(0xffffffffu, p, 8);
        p += __shfl_xor_sync(0xffffffffu, p, 4);
        p += __shfl_xor_sync(0xffffffffu, p, 2);
        p += __shfl_xor_sync(0xffffffffu, p, 1);
        if (s == 0) {
            float zz = g_xz[n * (2 * DI) + DI + d];
            g_y[n * DI + d] = (p + uu * Dv) * (zz * sigmoidf_(zz));
        }
    }
}

// ---------------- host orchestration --------------------------------------------
extern "C" void kernel_launch(void* const* d_in, const int* in_sizes, int n_in,
                              void* d_out, int out_size) {
    const float* x    = (const float*)d_in[0];
    const float* ln_g = (const float*)d_in[1];
    const float* ln_b = (const float*)d_in[2];
    const float* inw  = (const float*)d_in[3];   // [2,1024,256]
    const float* cw   = (const float*)d_in[4];   // [2,512,4]
    const float* cb   = (const float*)d_in[5];   // [2,512]
    const float* xpw  = (const float*)d_in[6];   // [2,48,512]
    const float* dtw  = (const float*)d_in[7];   // [2,512,16]
    const float* dtb  = (const float*)d_in[8];   // [2,512]
    const float* alog = (const float*)d_in[9];   // [2,512,16]
    const float* dp   = (const float*)d_in[10];  // [2,512]
    const float* ow   = (const float*)d_in[11];  // [2,256,512]
    const float* ls   = (const float*)d_in[12];  // [2,256]
    float* out = (float*)d_out;

    float *p_ln, *p_xz, *p_u, *p_xdbl, *p_dt, *p_y;
    cudaGetSymbolAddress((void**)&p_ln,   g_ln);
    cudaGetSymbolAddress((void**)&p_xz,   g_xz);
    cudaGetSymbolAddress((void**)&p_u,    g_u);
    cudaGetSymbolAddress((void**)&p_xdbl, g_xdbl);
    cudaGetSymbolAddress((void**)&p_dt,   g_dt);
    cudaGetSymbolAddress((void**)&p_y,    g_y);

    for (int i = 0; i < 2; i++) {
        const float* xin = (i == 0) ? x : out;

        // 1) layernorm
        ln_kernel<<<NTOK / 8, 256>>>(xin, ln_g + i * DM, ln_b + i * DM);

        // 2) in_proj: [N,256] x [1024,256]^T -> [N,1024]
        gemm_tn<128, 64, 16, 8, 4, 0><<<dim3((2 * DI) / 64, NTOK / 128), 256>>>(
            p_ln, DM, inw + (size_t)i * 2 * DI * DM, p_xz, 2 * DI, DM, nullptr, nullptr);

        // 3) causal conv4 + bias + SiLU on u-half
        conv_silu_kernel<<<(NTOK * DI) / 256, 256>>>(cw + i * DI * 4, cb + i * DI);

        // 4) x_proj: [N,512] x [48,512]^T -> [N,48]
        gemm_tn<64, 48, 16, 4, 3, 0><<<dim3(1, NTOK / 64), 256>>>(
            p_u, DI, xpw + (size_t)i * 48 * DI, p_xdbl, 48, DI, nullptr, nullptr);

        // 5) dt_proj + softplus: [N,16] x [512,16]^T -> [N,512]
        gemm_tn<128, 64, 16, 8, 4, 2><<<dim3(DI / 64, NTOK / 128), 256>>>(
            p_xdbl, 48, dtw + (size_t)i * DI * 16, p_dt, DI, 16, nullptr, dtb + i * DI);

        // 6) selective scan + D skip + z gating
        scan_kernel<<<(BATCH * DI) / 16, 256>>>(alog + (size_t)i * DI * DS, dp + i * DI);

        // 7) out_proj fused with residual + layer_scale: out = xin + ls * (y @ ow^T)
        gemm_tn<128, 64, 16, 8, 4, 1><<<dim3(DM / 64, NTOK / 128), 256>>>(
            p_y, DI, ow + (size_t)i * DM * DI, out, DM, DI, xin, ls + i * DM);
    }
}

// round 2
// speedup vs baseline: 2.5569x; 2.5569x over previous
#include <cuda_runtime.h>
#include <math.h>

#define NTOK  16384
#define BATCH 8
#define SEQ   2048
#define DM    256
#define DI    512
#define DS    16

// ---------------- scratch (allocation-free: __device__ globals) ----------------
__device__ float g_ln[NTOK * DM];        // layernorm output
__device__ float g_xz[NTOK * 2 * DI];    // in_proj output (u | z)
__device__ float g_u[NTOK * DI];         // conv+silu output
__device__ float g_xdbl[NTOK * 48];      // x_proj output (dt_r | B | C)
__device__ float g_dt[NTOK * DI];        // softplus(dt)
__device__ float g_y[NTOK * DI];         // scan output, gated

__device__ __forceinline__ float sigmoidf_(float v) { return 1.f / (1.f + __expf(-v)); }

// ---------------- layernorm: one warp per token (256 feats, 8/lane) ------------
__global__ void ln_kernel(const float* __restrict__ x,
                          const float* __restrict__ g,
                          const float* __restrict__ b) {
    int warp = threadIdx.x >> 5, lane = threadIdx.x & 31;
    int tok = blockIdx.x * 8 + warp;
    const float* row = x + (size_t)tok * DM;
    float v[8];
    float s = 0.f, s2 = 0.f;
#pragma unroll
    for (int i = 0; i < 8; i++) {
        v[i] = row[lane + i * 32];
        s += v[i];
        s2 += v[i] * v[i];
    }
#pragma unroll
    for (int o = 16; o; o >>= 1) {
        s  += __shfl_xor_sync(0xffffffffu, s, o);
        s2 += __shfl_xor_sync(0xffffffffu, s2, o);
    }
    float m   = s * (1.f / DM);
    float var = s2 * (1.f / DM) - m * m;
    float inv = rsqrtf(var + 1e-5f);
    float* o = g_ln + (size_t)tok * DM;
#pragma unroll
    for (int i = 0; i < 8; i++) {
        int c = lane + i * 32;
        o[c] = (v[i] - m) * inv * g[c] + b[c];
    }
}

// ------------- big tiled GEMM 128x128x16, float4 IO: C = A[M,K] * W[N,K]^T -----
// EPI: 0 = plain store, 1 = res + ls[n]*acc
template <int EPI>
__global__ __launch_bounds__(256)
void gemm_big(const float* __restrict__ A, int lda,
              const float* __restrict__ W,
              float* __restrict__ C,
              int N, int K,
              const float* __restrict__ res,
              const float* __restrict__ ls) {
    constexpr int BM = 128, BN = 128, BK = 16;
    __shared__ float As[BK][BM + 4];
    __shared__ float Ws[BK][BN + 4];
    const int tid = threadIdx.x;
    const int tx = tid & 15, ty = tid >> 4;            // 16x16 thread grid
    const int m0 = blockIdx.y * BM, n0 = blockIdx.x * BN;

    float acc[8][8];
#pragma unroll
    for (int i = 0; i < 8; i++)
#pragma unroll
        for (int j = 0; j < 8; j++) acc[i][j] = 0.f;

    for (int k0 = 0; k0 < K; k0 += BK) {
        // load A tile: 128x16 = 512 float4s, 2 per thread
#pragma unroll
        for (int t = 0; t < 2; t++) {
            int fidx = tid + t * 256;
            int m = fidx >> 2, k4 = (fidx & 3) << 2;
            float4 v = *(const float4*)&A[(size_t)(m0 + m) * lda + k0 + k4];
            As[k4 + 0][m] = v.x; As[k4 + 1][m] = v.y;
            As[k4 + 2][m] = v.z; As[k4 + 3][m] = v.w;
        }
#pragma unroll
        for (int t = 0; t < 2; t++) {
            int fidx = tid + t * 256;
            int n = fidx >> 2, k4 = (fidx & 3) << 2;
            float4 v = *(const float4*)&W[(size_t)(n0 + n) * K + k0 + k4];
            Ws[k4 + 0][n] = v.x; Ws[k4 + 1][n] = v.y;
            Ws[k4 + 2][n] = v.z; Ws[k4 + 3][n] = v.w;
        }
        __syncthreads();
#pragma unroll
        for (int kk = 0; kk < BK; kk++) {
            float a[8], w[8];
            *(float4*)&a[0] = *(const float4*)&As[kk][ty * 8];
            *(float4*)&a[4] = *(const float4*)&As[kk][ty * 8 + 4];
            *(float4*)&w[0] = *(const float4*)&Ws[kk][tx * 8];
            *(float4*)&w[4] = *(const float4*)&Ws[kk][tx * 8 + 4];
#pragma unroll
            for (int i = 0; i < 8; i++)
#pragma unroll
                for (int j = 0; j < 8; j++) acc[i][j] = fmaf(a[i], w[j], acc[i][j]);
        }
        __syncthreads();
    }

#pragma unroll
    for (int i = 0; i < 8; i++) {
        int m = m0 + ty * 8 + i;
#pragma unroll
        for (int j4 = 0; j4 < 2; j4++) {
            int n = n0 + tx * 8 + j4 * 4;
            float4 v;
            v.x = acc[i][j4 * 4 + 0]; v.y = acc[i][j4 * 4 + 1];
            v.z = acc[i][j4 * 4 + 2]; v.w = acc[i][j4 * 4 + 3];
            if (EPI == 1) {
                float4 rr = *(const float4*)&res[(size_t)m * N + n];
                v.x = rr.x + ls[n + 0] * v.x;
                v.y = rr.y + ls[n + 1] * v.y;
                v.z = rr.z + ls[n + 2] * v.z;
                v.w = rr.w + ls[n + 3] * v.w;
            }
            *(float4*)&C[(size_t)m * N + n] = v;
        }
    }
}

// ---------------- small tiled GEMM (odd shapes): C = A[M,K] * W[N,K]^T ----------
// EPI: 0 = plain store, 2 = softplus(acc + bias[n])
template <int BM, int BN, int BK, int TM, int TN, int EPI>
__global__ __launch_bounds__((BM / TM) * (BN / TN))
void gemm_tn(const float* __restrict__ A, int lda,
             const float* __restrict__ W,
             float* __restrict__ C,
             int N, int K,
             const float* __restrict__ v1) {
    constexpr int TX = BN / TN, TY = BM / TM, NT = TX * TY;
    __shared__ float As[BK][BM + 4];
    __shared__ float Ws[BK][BN + 4];
    const int tid = threadIdx.x;
    const int tx = tid % TX, ty = tid / TX;
    const int m0 = blockIdx.y * BM, n0 = blockIdx.x * BN;

    float acc[TM][TN];
#pragma unroll
    for (int i = 0; i < TM; i++)
#pragma unroll
        for (int j = 0; j < TN; j++) acc[i][j] = 0.f;

    for (int k0 = 0; k0 < K; k0 += BK) {
#pragma unroll
        for (int t = 0; t < (BM * BK) / NT; t++) {
            int idx = tid + t * NT;
            int i = idx / BK, k = idx % BK;
            As[k][i] = A[(size_t)(m0 + i) * lda + k0 + k];
        }
#pragma unroll
        for (int t = 0; t < (BN * BK) / NT; t++) {
            int idx = tid + t * NT;
            int i = idx / BK, k = idx % BK;
            Ws[k][i] = W[(size_t)(n0 + i) * K + k0 + k];
        }
        __syncthreads();
#pragma unroll
        for (int kk = 0; kk < BK; kk++) {
            float a[TM], w[TN];
#pragma unroll
            for (int i = 0; i < TM; i++) a[i] = As[kk][ty * TM + i];
#pragma unroll
            for (int j = 0; j < TN; j++) w[j] = Ws[kk][tx * TN + j];
#pragma unroll
            for (int i = 0; i < TM; i++)
#pragma unroll
                for (int j = 0; j < TN; j++) acc[i][j] = fmaf(a[i], w[j], acc[i][j]);
        }
        __syncthreads();
    }

#pragma unroll
    for (int i = 0; i < TM; i++) {
        int m = m0 + ty * TM + i;
#pragma unroll
        for (int j = 0; j < TN; j++) {
            int n = n0 + tx * TN + j;
            float v = acc[i][j];
            if (EPI == 2) {
                v += v1[n];
                v = (v > 20.f) ? v : log1pf(__expf(v));  // softplus
            }
            C[(size_t)m * N + n] = v;
        }
    }
}

// ---------------- causal depthwise conv(4) + bias + SiLU ------------------------
__global__ void conv_silu_kernel(const float* __restrict__ cw,
                                 const float* __restrict__ cb) {
    int idx = blockIdx.x * blockDim.x + threadIdx.x;  // over NTOK*DI
    int d = idx & (DI - 1);
    int n = idx >> 9;         // token index (b*SEQ + l)
    int l = n & (SEQ - 1);
    float acc = cb[d];
    const float* w = cw + d * 4;
#pragma unroll
    for (int j = 0; j < 4; j++) {
        int ll = l - 3 + j;
        if (ll >= 0) acc = fmaf(w[j], g_xz[(size_t)(n - 3 + j) * (2 * DI) + d], acc);
    }
    g_u[idx] = acc * sigmoidf_(acc);
}

// ---------------- selective scan: 16 lanes per (b,d) channel --------------------
// block = 256 threads = 16 channels (same batch b). Chunked 16-deep prefetch so
// load latency is exposed once per 16 steps instead of every step.
#define TCH 16
__global__ __launch_bounds__(256)
void scan_kernel(const float* __restrict__ A_log,
                 const float* __restrict__ Dp) {
    int tid = threadIdx.x;
    int half = tid >> 4;              // channel within block (0..15)
    int s = tid & 15;                 // state index
    int b = blockIdx.x >> 5;          // 32 blocks per batch (512/16)
    int d = ((blockIdx.x & 31) << 4) + half;

    float As = -__expf(A_log[d * DS + s]);
    float Dv = Dp[d];
    float h = 0.f;
    size_t base = (size_t)b * SEQ;

    for (int l0 = 0; l0 < SEQ; l0 += TCH) {
        float r[TCH], uu[TCH], Bv[TCH], Cv[TCH], gz[TCH];
#pragma unroll
        for (int t = 0; t < TCH; t++) {
            size_t n = base + l0 + t;
            r[t]  = g_dt[n * DI + d];
            uu[t] = g_u[n * DI + d];
            Bv[t] = g_xdbl[n * 48 + 16 + s];
            Cv[t] = g_xdbl[n * 48 + 32 + s];
            gz[t] = g_xz[n * (2 * DI) + DI + d];   // broadcast within group
        }
#pragma unroll
        for (int t = 0; t < TCH; t++) {
            float dA = __expf(r[t] * As);
            h = fmaf(dA, h, (r[t] * uu[t]) * Bv[t]);
            float p = h * Cv[t];
            p += __shfl_xor_sync(0xffffffffu, p, 8);
            p += __shfl_xor_sync(0xffffffffu, p, 4);
            p += __shfl_xor_sync(0xffffffffu, p, 2);
            p += __shfl_xor_sync(0xffffffffu, p, 1);
            if (s == 0) {
                float zz = gz[t];
                g_y[(base + l0 + t) * DI + d] = (p + uu[t] * Dv) * (zz * sigmoidf_(zz));
            }
        }
    }
}

// ---------------- host orchestration --------------------------------------------
extern "C" void kernel_launch(void* const* d_in, const int* in_sizes, int n_in,
                              void* d_out, int out_size) {
    const float* x    = (const float*)d_in[0];
    const float* ln_g = (const float*)d_in[1];
    const float* ln_b = (const float*)d_in[2];
    const float* inw  = (const float*)d_in[3];   // [2,1024,256]
    const float* cw   = (const float*)d_in[4];   // [2,512,4]
    const float* cb   = (const float*)d_in[5];   // [2,512]
    const float* xpw  = (const float*)d_in[6];   // [2,48,512]
    const float* dtw  = (const float*)d_in[7];   // [2,512,16]
    const float* dtb  = (const float*)d_in[8];   // [2,512]
    const float* alog = (const float*)d_in[9];   // [2,512,16]
    const float* dp   = (const float*)d_in[10];  // [2,512]
    const float* ow   = (const float*)d_in[11];  // [2,256,512]
    const float* ls   = (const float*)d_in[12];  // [2,256]
    float* out = (float*)d_out;

    float *p_ln, *p_xz, *p_u, *p_xdbl, *p_dt, *p_y;
    cudaGetSymbolAddress((void**)&p_ln,   g_ln);
    cudaGetSymbolAddress((void**)&p_xz,   g_xz);
    cudaGetSymbolAddress((void**)&p_u,    g_u);
    cudaGetSymbolAddress((void**)&p_xdbl, g_xdbl);
    cudaGetSymbolAddress((void**)&p_dt,   g_dt);
    cudaGetSymbolAddress((void**)&p_y,    g_y);

    for (int i = 0; i < 2; i++) {
        const float* xin = (i == 0) ? x : out;

        // 1) layernorm
        ln_kernel<<<NTOK / 8, 256>>>(xin, ln_g + i * DM, ln_b + i * DM);

        // 2) in_proj: [N,256] x [1024,256]^T -> [N,1024]
        gemm_big<0><<<dim3((2 * DI) / 128, NTOK / 128), 256>>>(
            p_ln, DM, inw + (size_t)i * 2 * DI * DM, p_xz, 2 * DI, DM, nullptr, nullptr);

        // 3) causal conv4 + bias + SiLU on u-half
        conv_silu_kernel<<<(NTOK * DI) / 256, 256>>>(cw + i * DI * 4, cb + i * DI);

        // 4) x_proj: [N,512] x [48,512]^T -> [N,48]
        gemm_tn<64, 48, 16, 4, 3, 0><<<dim3(1, NTOK / 64), 256>>>(
            p_u, DI, xpw + (size_t)i * 48 * DI, p_xdbl, 48, DI, nullptr);

        // 5) dt_proj + softplus: [N,16] x [512,16]^T -> [N,512]
        gemm_tn<128, 64, 16, 8, 4, 2><<<dim3(DI / 64, NTOK / 128), 256>>>(
            p_xdbl, 48, dtw + (size_t)i * DI * 16, p_dt, DI, 16, dtb + i * DI);

        // 6) selective scan + D skip + z gating
        scan_kernel<<<(BATCH * DI) / 16, 256>>>(alog + (size_t)i * DI * DS, dp + i * DI);

        // 7) out_proj fused with residual + layer_scale: out = xin + ls * (y @ ow^T)
        gemm_big<1><<<dim3(DM / 128, NTOK / 128), 256>>>(
            p_y, DI, ow + (size_t)i * DM * DI, out, DM, DI, xin, ls + i * DM);
    }
}

// round 7
// speedup vs baseline: 3.3308x; 1.3027x over previous
#include <cuda_runtime.h>
#include <stdint.h>
#include <math.h>

#define NTOK  16384
#define BATCH 8
#define SEQ   2048
#define DM    256
#define DI    512
#define DS    16

// ---------------- scratch (allocation-free: __device__ globals) ----------------
__device__ float g_ln[NTOK * DM];        // layernorm output
__device__ float g_xz[NTOK * 2 * DI];    // in_proj output (u | z)
__device__ float g_u[NTOK * DI];         // conv+silu output
__device__ float g_xdbl[NTOK * 48];      // x_proj output (dt_r | B | C)
__device__ float g_dt[NTOK * DI];        // softplus(dt)
__device__ float g_y[NTOK * DI];         // scan output, gated

__device__ __forceinline__ float sigmoidf_(float v) { return 1.f / (1.f + __expf(-v)); }

__device__ __forceinline__ float to_tf32(float x) {
    unsigned int u;
    asm("cvt.rna.tf32.f32 %0, %1;" : "=r"(u) : "f"(x));
    return __uint_as_float(u);
}

// ---------------- layernorm: one warp per token (256 feats, 8/lane) ------------
__global__ void ln_kernel(const float* __restrict__ x,
                          const float* __restrict__ g,
                          const float* __restrict__ b) {
    int warp = threadIdx.x >> 5, lane = threadIdx.x & 31;
    int tok = blockIdx.x * 8 + warp;
    const float* row = x + (size_t)tok * DM;
    float v[8];
    float s = 0.f, s2 = 0.f;
#pragma unroll
    for (int i = 0; i < 8; i++) {
        v[i] = row[lane + i * 32];
        s += v[i];
        s2 += v[i] * v[i];
    }
#pragma unroll
    for (int o = 16; o; o >>= 1) {
        s  += __shfl_xor_sync(0xffffffffu, s, o);
        s2 += __shfl_xor_sync(0xffffffffu, s2, o);
    }
    float m   = s * (1.f / DM);
    float var = s2 * (1.f / DM) - m * m;
    float inv = rsqrtf(var + 1e-5f);
    float* o = g_ln + (size_t)tok * DM;
#pragma unroll
    for (int i = 0; i < 8; i++) {
        int c = lane + i * 32;
        o[c] = (v[i] - m) * inv * g[c] + b[c];
    }
}

// ------------- TF32 tensor-core GEMM: C[M,N] = A[M,K] * W[N,K]^T ----------------
// Block tile 128x64x32, 8 warps, warp tile 32x32 (2 m-frags x 4 n-frags m16n8k8).
// EPI: 0 = plain store, 1 = res + ls[n]*acc.  NVALID: valid N columns (<=64).
template <int EPI, int NVALID>
__global__ __launch_bounds__(256)
void gemm_mma(const float* __restrict__ A, int lda,
              const float* __restrict__ W,
              float* __restrict__ C,
              int N, int K,
              const float* __restrict__ res,
              const float* __restrict__ ls) {
    __shared__ float As[32][132];   // [k][m], stride 132 -> conflict-free frags
    __shared__ float Ws[32][68];    // [k][n], stride 68

    const int tid = threadIdx.x;
    const int warp = tid >> 5, lane = tid & 31;
    const int wm = (warp >> 1) * 32;         // warp m offset in tile (4 rows of warps)
    const int wn = (warp & 1) * 32;          // warp n offset (2 cols of warps)
    const int m0 = blockIdx.y * 128, n0 = blockIdx.x * 64;
    const int lq = lane >> 2, lp = lane & 3;

    float acc[2][4][4];
#pragma unroll
    for (int i = 0; i < 2; i++)
#pragma unroll
        for (int j = 0; j < 4; j++)
#pragma unroll
            for (int q = 0; q < 4; q++) acc[i][j][q] = 0.f;

    for (int k0 = 0; k0 < K; k0 += 32) {
        // A tile: 128x32 = 1024 float4, 4 per thread
#pragma unroll
        for (int t = 0; t < 4; t++) {
            int fidx = tid + t * 256;
            int m = fidx >> 3, kp = (fidx & 7) << 2;
            float4 v = *(const float4*)&A[(size_t)(m0 + m) * lda + k0 + kp];
            As[kp + 0][m] = to_tf32(v.x); As[kp + 1][m] = to_tf32(v.y);
            As[kp + 2][m] = to_tf32(v.z); As[kp + 3][m] = to_tf32(v.w);
        }
        // W tile: 64x32 = 512 float4, 2 per thread
#pragma unroll
        for (int t = 0; t < 2; t++) {
            int fidx = tid + t * 256;
            int n = fidx >> 3, kp = (fidx & 7) << 2;
            float4 v;
            if (NVALID == 64 || n < NVALID)
                v = *(const float4*)&W[(size_t)(n0 + n) * K + k0 + kp];
            else
                v = make_float4(0.f, 0.f, 0.f, 0.f);
            Ws[kp + 0][n] = to_tf32(v.x); Ws[kp + 1][n] = to_tf32(v.y);
            Ws[kp + 2][n] = to_tf32(v.z); Ws[kp + 3][n] = to_tf32(v.w);
        }
        __syncthreads();

#pragma unroll
        for (int kk = 0; kk < 4; kk++) {
            const int kb = kk * 8;
            unsigned int a[2][4], b[4][2];
#pragma unroll
            for (int mf = 0; mf < 2; mf++) {
                int r = wm + mf * 16 + lq;
                int c = kb + lp;
                a[mf][0] = __float_as_uint(As[c][r]);
                a[mf][1] = __float_as_uint(As[c][r + 8]);
                a[mf][2] = __float_as_uint(As[c + 4][r]);
                a[mf][3] = __float_as_uint(As[c + 4][r + 8]);
            }
#pragma unroll
            for (int nf = 0; nf < 4; nf++) {
                int n = wn + nf * 8 + lq;
                b[nf][0] = __float_as_uint(Ws[kb + lp][n]);
                b[nf][1] = __float_as_uint(Ws[kb + 4 + lp][n]);
            }
#pragma unroll
            for (int mf = 0; mf < 2; mf++)
#pragma unroll
                for (int nf = 0; nf < 4; nf++) {
                    asm volatile(
                        "mma.sync.aligned.m16n8k8.row.col.f32.tf32.tf32.f32 "
                        "{%0,%1,%2,%3},{%4,%5,%6,%7},{%8,%9},{%0,%1,%2,%3};"
                        : "+f"(acc[mf][nf][0]), "+f"(acc[mf][nf][1]),
                          "+f"(acc[mf][nf][2]), "+f"(acc[mf][nf][3])
                        : "r"(a[mf][0]), "r"(a[mf][1]), "r"(a[mf][2]), "r"(a[mf][3]),
                          "r"(b[nf][0]), "r"(b[nf][1]));
                }
        }
        __syncthreads();
    }

    // epilogue: each thread owns float2 pairs at (r, c0) and (r+8, c0)
#pragma unroll
    for (int mf = 0; mf < 2; mf++) {
#pragma unroll
        for (int nf = 0; nf < 4; nf++) {
            int r0 = m0 + wm + mf * 16 + lq;
            int c0 = n0 + wn + nf * 8 + lp * 2;
            if (NVALID < 64 && c0 >= NVALID) continue;
            float2 v0 = make_float2(acc[mf][nf][0], acc[mf][nf][1]);
            float2 v1 = make_float2(acc[mf][nf][2], acc[mf][nf][3]);
            if (EPI == 1) {
                float2 r0v = *(const float2*)&res[(size_t)r0 * N + c0];
                float2 r1v = *(const float2*)&res[(size_t)(r0 + 8) * N + c0];
                float l0 = ls[c0], l1 = ls[c0 + 1];
                v0.x = r0v.x + l0 * v0.x; v0.y = r0v.y + l1 * v0.y;
                v1.x = r1v.x + l0 * v1.x; v1.y = r1v.y + l1 * v1.y;
            }
            *(float2*)&C[(size_t)r0 * N + c0] = v0;
            *(float2*)&C[(size_t)(r0 + 8) * N + c0] = v1;
        }
    }
}

// ---------------- small tiled GEMM (dt_proj): C = A[M,K] * W[N,K]^T -------------
// EPI: 2 = softplus(acc + bias[n])
template <int BM, int BN, int BK, int TM, int TN, int EPI>
__global__ __launch_bounds__((BM / TM) * (BN / TN))
void gemm_tn(const float* __restrict__ A, int lda,
             const float* __restrict__ W,
             float* __restrict__ C,
             int N, int K,
             const float* __restrict__ v1) {
    constexpr int TX = BN / TN, TY = BM / TM, NT = TX * TY;
    __shared__ float As[BK][BM + 4];
    __shared__ float Ws[BK][BN + 4];
    const int tid = threadIdx.x;
    const int tx = tid % TX, ty = tid / TX;
    const int m0 = blockIdx.y * BM, n0 = blockIdx.x * BN;

    float acc[TM][TN];
#pragma unroll
    for (int i = 0; i < TM; i++)
#pragma unroll
        for (int j = 0; j < TN; j++) acc[i][j] = 0.f;

    for (int k0 = 0; k0 < K; k0 += BK) {
#pragma unroll
        for (int t = 0; t < (BM * BK) / NT; t++) {
            int idx = tid + t * NT;
            int i = idx / BK, k = idx % BK;
            As[k][i] = A[(size_t)(m0 + i) * lda + k0 + k];
        }
#pragma unroll
        for (int t = 0; t < (BN * BK) / NT; t++) {
            int idx = tid + t * NT;
            int i = idx / BK, k = idx % BK;
            Ws[k][i] = W[(size_t)(n0 + i) * K + k0 + k];
        }
        __syncthreads();
#pragma unroll
        for (int kk = 0; kk < BK; kk++) {
            float a[TM], w[TN];
#pragma unroll
            for (int i = 0; i < TM; i++) a[i] = As[kk][ty * TM + i];
#pragma unroll
            for (int j = 0; j < TN; j++) w[j] = Ws[kk][tx * TN + j];
#pragma unroll
            for (int i = 0; i < TM; i++)
#pragma unroll
                for (int j = 0; j < TN; j++) acc[i][j] = fmaf(a[i], w[j], acc[i][j]);
        }
        __syncthreads();
    }

#pragma unroll
    for (int i = 0; i < TM; i++) {
        int m = m0 + ty * TM + i;
#pragma unroll
        for (int j = 0; j < TN; j++) {
            int n = n0 + tx * TN + j;
            float v = acc[i][j];
            if (EPI == 2) {
                v += v1[n];
                v = (v > 20.f) ? v : log1pf(__expf(v));  // softplus
            }
            C[(size_t)m * N + n] = v;
        }
    }
}

// ---------------- causal depthwise conv(4) + bias + SiLU ------------------------
__global__ void conv_silu_kernel(const float* __restrict__ cw,
                                 const float* __restrict__ cb) {
    int idx = blockIdx.x * blockDim.x + threadIdx.x;  // over NTOK*DI
    int d = idx & (DI - 1);
    int n = idx >> 9;         // token index (b*SEQ + l)
    int l = n & (SEQ - 1);
    float acc = cb[d];
    const float* w = cw + d * 4;
#pragma unroll
    for (int j = 0; j < 4; j++) {
        int ll = l - 3 + j;
        if (ll >= 0) acc = fmaf(w[j], g_xz[(size_t)(n - 3 + j) * (2 * DI) + d], acc);
    }
    g_u[idx] = acc * sigmoidf_(acc);
}

// ---------------- selective scan: smem-staged, 16 lanes per (b,d) channel -------
// block = 256 threads = 16 channels (same batch b, consecutive d).
// Per 16-step chunk: 5 coalesced LDG/thread prefetched into registers during the
// previous chunk's compute, then served from conflict-free smem.
#define TCH 16
__global__ __launch_bounds__(256)
void scan_kernel(const float* __restrict__ A_log,
                 const float* __restrict__ Dp) {
    __shared__ float sdt[TCH][16], su[TCH][16], sz[TCH][16], sB[TCH][16], sC[TCH][16];

    int tid = threadIdx.x;
    int half = tid >> 4;              // channel within block (0..15)
    int s = tid & 15;                 // state index
    int b = blockIdx.x >> 5;          // 32 blocks per batch (512/16)
    int d0 = (blockIdx.x & 31) << 4;
    int d = d0 + half;

    float As = -__expf(A_log[d * DS + s]);
    float Dv = Dp[d];
    float h = 0.f;
    size_t base = (size_t)b * SEQ;

    // loading role: thread (t, j) loads timestep t, channel/state j
    int lt = tid >> 4, lj = tid & 15;

    float p_dt, p_u, p_z, p_B, p_C;
    {
        size_t n = base + lt;
        p_dt = g_dt[n * DI + d0 + lj];
        p_u  = g_u [n * DI + d0 + lj];
        p_z  = g_xz[n * (2 * DI) + DI + d0 + lj];
        p_B  = g_xdbl[n * 48 + 16 + lj];
        p_C  = g_xdbl[n * 48 + 32 + lj];
    }

    for (int l0 = 0; l0 < SEQ; l0 += TCH) {
        __syncthreads();   // previous chunk's compute done
        sdt[lt][lj] = p_dt; su[lt][lj] = p_u; sz[lt][lj] = p_z;
        sB[lt][lj]  = p_B;  sC[lt][lj] = p_C;
        __syncthreads();

        if (l0 + TCH < SEQ) {   // prefetch next chunk (overlaps compute below)
            size_t n = base + l0 + TCH + lt;
            p_dt = g_dt[n * DI + d0 + lj];
            p_u  = g_u [n * DI + d0 + lj];
            p_z  = g_xz[n * (2 * DI) + DI + d0 + lj];
            p_B  = g_xdbl[n * 48 + 16 + lj];
            p_C  = g_xdbl[n * 48 + 32 + lj];
        }

#pragma unroll
        for (int t = 0; t < TCH; t++) {
            float r  = sdt[t][half];
            float uu = su[t][half];
            float Bv = sB[t][s];
            float Cv = sC[t][s];
            float dA = __expf(r * As);
            h = fmaf(dA, h, (r * uu) * Bv);
            float p = h * Cv;
            p += __shfl_xor_sync(0xffffffffu, p, 8);
            p += __shfl_xor_sync(0xffffffffu, p, 4);
            p += __shfl_xor_sync(0xffffffffu, p, 2);
            p += __shfl_xor_sync(0xffffffffu, p, 1);
            if (s == 0) {
                float zz = sz[t][half];
                g_y[(base + l0 + t) * DI + d] = (p + uu * Dv) * (zz * sigmoidf_(zz));
            }
        }
    }
}

// ---------------- host orchestration --------------------------------------------
extern "C" void kernel_launch(void* const* d_in, const int* in_sizes, int n_in,
                              void* d_out, int out_size) {
    const float* x    = (const float*)d_in[0];
    const float* ln_g = (const float*)d_in[1];
    const float* ln_b = (const float*)d_in[2];
    const float* inw  = (const float*)d_in[3];   // [2,1024,256]
    const float* cw   = (const float*)d_in[4];   // [2,512,4]
    const float* cb   = (const float*)d_in[5];   // [2,512]
    const float* xpw  = (const float*)d_in[6];   // [2,48,512]
    const float* dtw  = (const float*)d_in[7];   // [2,512,16]
    const float* dtb  = (const float*)d_in[8];   // [2,512]
    const float* alog = (const float*)d_in[9];   // [2,512,16]
    const float* dp   = (const float*)d_in[10];  // [2,512]
    const float* ow   = (const float*)d_in[11];  // [2,256,512]
    const float* ls   = (const float*)d_in[12];  // [2,256]
    float* out = (float*)d_out;

    float *p_ln, *p_xz, *p_u, *p_xdbl, *p_dt, *p_y;
    cudaGetSymbolAddress((void**)&p_ln,   g_ln);
    cudaGetSymbolAddress((void**)&p_xz,   g_xz);
    cudaGetSymbolAddress((void**)&p_u,    g_u);
    cudaGetSymbolAddress((void**)&p_xdbl, g_xdbl);
    cudaGetSymbolAddress((void**)&p_dt,   g_dt);
    cudaGetSymbolAddress((void**)&p_y,    g_y);

    for (int i = 0; i < 2; i++) {
        const float* xin = (i == 0) ? x : out;

        // 1) layernorm
        ln_kernel<<<NTOK / 8, 256>>>(xin, ln_g + i * DM, ln_b + i * DM);

        // 2) in_proj: [N,256] x [1024,256]^T -> [N,1024]   (tf32 mma)
        gemm_mma<0, 64><<<dim3((2 * DI) / 64, NTOK / 128), 256>>>(
            p_ln, DM, inw + (size_t)i * 2 * DI * DM, p_xz, 2 * DI, DM, nullptr, nullptr);

        // 3) causal conv4 + bias + SiLU on u-half
        conv_silu_kernel<<<(NTOK * DI) / 256, 256>>>(cw + i * DI * 4, cb + i * DI);

        // 4) x_proj: [N,512] x [48,512]^T -> [N,48]   (tf32 mma, N padded to 64)
        gemm_mma<0, 48><<<dim3(1, NTOK / 128), 256>>>(
            p_u, DI, xpw + (size_t)i * 48 * DI, p_xdbl, 48, DI, nullptr, nullptr);

        // 5) dt_proj + softplus: [N,16] x [512,16]^T -> [N,512]
        gemm_tn<128, 64, 16, 8, 4, 2><<<dim3(DI / 64, NTOK / 128), 256>>>(
            p_xdbl, 48, dtw + (size_t)i * DI * 16, p_dt, DI, 16, dtb + i * DI);

        // 6) selective scan + D skip + z gating
        scan_kernel<<<(BATCH * DI) / 16, 256>>>(alog + (size_t)i * DI * DS, dp + i * DI);

        // 7) out_proj fused with residual + layer_scale: out = xin + ls * (y @ ow^T)
        gemm_mma<1, 64><<<dim3(DM / 64, NTOK / 128), 256>>>(
            p_y, DI, ow + (size_t)i * DM * DI, out, DM, DI, xin, ls + i * DM);
    }
}

// round 8
// speedup vs baseline: 3.9696x; 1.1918x over previous
#include <cuda_runtime.h>
#include <stdint.h>
#include <math.h>

#define NTOK  16384
#define BATCH 8
#define SEQ   2048
#define DM    256
#define DI    512
#define DS    16

// ---------------- scratch (allocation-free: __device__ globals) ----------------
__device__ float g_ln[NTOK * DM];        // layernorm output
__device__ float g_xz[NTOK * 2 * DI];    // in_proj output (u | z)
__device__ float g_u[NTOK * DI];         // conv+silu output
__device__ float g_xdbl[NTOK * 48];      // x_proj output (dt_r | B | C)
__device__ float g_y[NTOK * DI];         // scan output, gated

__device__ __forceinline__ float sigmoidf_(float v) { return 1.f / (1.f + __expf(-v)); }

__device__ __forceinline__ unsigned smem_u32(const void* p) {
    return (unsigned)__cvta_generic_to_shared(p);
}
__device__ __forceinline__ void cp16(unsigned dst, const float* src) {
    asm volatile("cp.async.cg.shared.global [%0], [%1], 16;" :: "r"(dst), "l"(src));
}

// ---------------- layernorm: one warp per token (256 feats, 8/lane) ------------
__global__ void ln_kernel(const float* __restrict__ x,
                          const float* __restrict__ g,
                          const float* __restrict__ b) {
    int warp = threadIdx.x >> 5, lane = threadIdx.x & 31;
    int tok = blockIdx.x * 8 + warp;
    const float* row = x + (size_t)tok * DM;
    float v[8];
    float s = 0.f, s2 = 0.f;
#pragma unroll
    for (int i = 0; i < 8; i++) {
        v[i] = row[lane + i * 32];
        s += v[i];
        s2 += v[i] * v[i];
    }
#pragma unroll
    for (int o = 16; o; o >>= 1) {
        s  += __shfl_xor_sync(0xffffffffu, s, o);
        s2 += __shfl_xor_sync(0xffffffffu, s2, o);
    }
    float m   = s * (1.f / DM);
    float var = s2 * (1.f / DM) - m * m;
    float inv = rsqrtf(var + 1e-5f);
    float* o = g_ln + (size_t)tok * DM;
#pragma unroll
    for (int i = 0; i < 8; i++) {
        int c = lane + i * 32;
        o[c] = (v[i] - m) * inv * g[c] + b[c];
    }
}

// ------------- TF32 tensor-core GEMM, cp.async double-buffered ------------------
// C[M,N] = A[M,K] * W[N,K]^T.  Block tile 128x64x32, 8 warps, warp tile 32x32.
// Smem row-major stride 36 floats (16B-aligned rows, conflict-free frag loads).
// EPI: 0 = plain store, 1 = res + ls[n]*acc.  NVALID: valid N columns (<=64).
#define AS_STR 36
#define AS_BUF (128 * AS_STR)
#define WS_BUF (64 * AS_STR)
#define GEMM_SMEM ((2 * AS_BUF + 2 * WS_BUF) * 4)

template <int EPI, int NVALID>
__global__ __launch_bounds__(256)
void gemm_mma(const float* __restrict__ A, int lda,
              const float* __restrict__ W,
              float* __restrict__ C,
              int N, int K,
              const float* __restrict__ res,
              const float* __restrict__ ls) {
    extern __shared__ float dyn[];
    float* As = dyn;                    // [2][128][36]
    float* Ws = dyn + 2 * AS_BUF;       // [2][64][36]

    const int tid = threadIdx.x;
    const int warp = tid >> 5, lane = tid & 31;
    const int wm = (warp >> 1) * 32;
    const int wn = (warp & 1) * 32;
    const int m0 = blockIdx.y * 128, n0 = blockIdx.x * 64;
    const int lq = lane >> 2, lp = lane & 3;

    // zero-pad invalid W rows once (never overwritten by cp.async)
    if (NVALID < 64) {
        for (int i = tid; i < 2 * WS_BUF; i += 256) {
            int row = (i % WS_BUF) / AS_STR;
            if (row >= NVALID) Ws[i] = 0.f;
        }
    }

    // loader roles
    const int la_m = 0; (void)la_m;

    auto issue_tile = [&](int buf, int k0) {
#pragma unroll
        for (int t = 0; t < 4; t++) {
            int fidx = tid + t * 256;
            int m = fidx >> 3, kc = fidx & 7;
            cp16(smem_u32(&As[buf * AS_BUF + m * AS_STR + kc * 4]),
                 &A[(size_t)(m0 + m) * lda + k0 + kc * 4]);
        }
#pragma unroll
        for (int t = 0; t < 2; t++) {
            int fidx = tid + t * 256;
            int n = fidx >> 3, kc = fidx & 7;
            if (NVALID == 64 || n < NVALID)
                cp16(smem_u32(&Ws[buf * WS_BUF + n * AS_STR + kc * 4]),
                     &W[(size_t)(n0 + n) * K + k0 + kc * 4]);
        }
        asm volatile("cp.async.commit_group;");
    };

    float acc[2][4][4];
#pragma unroll
    for (int i = 0; i < 2; i++)
#pragma unroll
        for (int j = 0; j < 4; j++)
#pragma unroll
            for (int q = 0; q < 4; q++) acc[i][j][q] = 0.f;

    const int nit = K / 32;
    issue_tile(0, 0);

    for (int it = 0; it < nit; it++) {
        int buf = it & 1;
        if (it + 1 < nit) {
            issue_tile(buf ^ 1, (it + 1) * 32);
            asm volatile("cp.async.wait_group 1;");
        } else {
            asm volatile("cp.async.wait_group 0;");
        }
        __syncthreads();

        const float* ab = As + buf * AS_BUF;
        const float* wb = Ws + buf * WS_BUF;
#pragma unroll
        for (int kk = 0; kk < 4; kk++) {
            const int kb = kk * 8;
            unsigned int a[2][4], b[4][2];
#pragma unroll
            for (int mf = 0; mf < 2; mf++) {
                int r = wm + mf * 16 + lq;
                a[mf][0] = __float_as_uint(ab[r * AS_STR + kb + lp]);
                a[mf][1] = __float_as_uint(ab[(r + 8) * AS_STR + kb + lp]);
                a[mf][2] = __float_as_uint(ab[r * AS_STR + kb + 4 + lp]);
                a[mf][3] = __float_as_uint(ab[(r + 8) * AS_STR + kb + 4 + lp]);
            }
#pragma unroll
            for (int nf = 0; nf < 4; nf++) {
                int n = wn + nf * 8 + lq;
                b[nf][0] = __float_as_uint(wb[n * AS_STR + kb + lp]);
                b[nf][1] = __float_as_uint(wb[n * AS_STR + kb + 4 + lp]);
            }
#pragma unroll
            for (int mf = 0; mf < 2; mf++)
#pragma unroll
                for (int nf = 0; nf < 4; nf++) {
                    asm volatile(
                        "mma.sync.aligned.m16n8k8.row.col.f32.tf32.tf32.f32 "
                        "{%0,%1,%2,%3},{%4,%5,%6,%7},{%8,%9},{%0,%1,%2,%3};"
                        : "+f"(acc[mf][nf][0]), "+f"(acc[mf][nf][1]),
                          "+f"(acc[mf][nf][2]), "+f"(acc[mf][nf][3])
                        : "r"(a[mf][0]), "r"(a[mf][1]), "r"(a[mf][2]), "r"(a[mf][3]),
                          "r"(b[nf][0]), "r"(b[nf][1]));
                }
        }
        __syncthreads();
    }

    // epilogue
#pragma unroll
    for (int mf = 0; mf < 2; mf++) {
#pragma unroll
        for (int nf = 0; nf < 4; nf++) {
            int r0 = m0 + wm + mf * 16 + lq;
            int c0 = n0 + wn + nf * 8 + lp * 2;
            if (NVALID < 64 && c0 >= NVALID) continue;
            float2 v0 = make_float2(acc[mf][nf][0], acc[mf][nf][1]);
            float2 v1 = make_float2(acc[mf][nf][2], acc[mf][nf][3]);
            if (EPI == 1) {
                float2 r0v = *(const float2*)&res[(size_t)r0 * N + c0];
                float2 r1v = *(const float2*)&res[(size_t)(r0 + 8) * N + c0];
                float l0 = ls[c0], l1 = ls[c0 + 1];
                v0.x = r0v.x + l0 * v0.x; v0.y = r0v.y + l1 * v0.y;
                v1.x = r1v.x + l0 * v1.x; v1.y = r1v.y + l1 * v1.y;
            }
            *(float2*)&C[(size_t)r0 * N + c0] = v0;
            *(float2*)&C[(size_t)(r0 + 8) * N + c0] = v1;
        }
    }
}

// ---------------- causal depthwise conv(4) + bias + SiLU ------------------------
__global__ void conv_silu_kernel(const float* __restrict__ cw,
                                 const float* __restrict__ cb) {
    int idx = blockIdx.x * blockDim.x + threadIdx.x;  // over NTOK*DI
    int d = idx & (DI - 1);
    int n = idx >> 9;         // token index (b*SEQ + l)
    int l = n & (SEQ - 1);
    float acc = cb[d];
    const float* w = cw + d * 4;
#pragma unroll
    for (int j = 0; j < 4; j++) {
        int ll = l - 3 + j;
        if (ll >= 0) acc = fmaf(w[j], g_xz[(size_t)(n - 3 + j) * (2 * DI) + d], acc);
    }
    g_u[idx] = acc * sigmoidf_(acc);
}

// ---------------- selective scan with fused dt_proj+softplus --------------------
// block = 256 threads = 16 channels (same batch b, consecutive d), 16 states each.
// Per 16-step chunk: stage xdbl rows (768 floats), u, z from registers (prefetched
// during previous chunk's compute); compute dt = softplus(xdbl[:16] . dtw[d] + b)
// in-block (16 FMA/thread); inner loop runs from conflict-free smem.
#define TCH 16
__global__ __launch_bounds__(256)
void scan_kernel(const float* __restrict__ A_log,
                 const float* __restrict__ Dp,
                 const float* __restrict__ dtw,   // [DI,16]
                 const float* __restrict__ dtb) { // [DI]
    __shared__ float sx[TCH * 48];       // xdbl rows for the chunk
    __shared__ float su_[TCH][16], sz_[TCH][16];
    __shared__ float sdtw[16][17];       // [r][j] : dtw[(d0+j)*16 + r]
    __shared__ float sdt_[TCH][16];

    int tid = threadIdx.x;
    int half = tid >> 4;              // channel within block (0..15)
    int s = tid & 15;                 // state index
    int b = blockIdx.x >> 5;          // 32 blocks per batch (512/16)
    int d0 = (blockIdx.x & 31) << 4;
    int d = d0 + half;

    int lt = tid >> 4, lj = tid & 15; // loading/compute role: (timestep, channel)

    {   // cache dt weights for this channel group
        int j = tid >> 4, r = tid & 15;
        sdtw[r][j] = dtw[(d0 + j) * 16 + r];
    }
    float dtb_j = dtb[d0 + lj];

    float As = -__expf(A_log[d * DS + s]);
    float Dv = Dp[d];
    float h = 0.f;
    size_t base = (size_t)b * SEQ;

    // prefetch chunk 0
    float p_x0, p_x1, p_x2, p_u, p_z;
    {
        const float* xrow = g_xdbl + base * 48;
        p_x0 = xrow[tid]; p_x1 = xrow[tid + 256]; p_x2 = xrow[tid + 512];
        size_t n = base + lt;
        p_u = g_u[n * DI + d0 + lj];
        p_z = g_xz[n * (2 * DI) + DI + d0 + lj];
    }

    for (int l0 = 0; l0 < SEQ; l0 += TCH) {
        __syncthreads();   // previous chunk's compute done
        sx[tid] = p_x0; sx[tid + 256] = p_x1; sx[tid + 512] = p_x2;
        su_[lt][lj] = p_u; sz_[lt][lj] = p_z;
        __syncthreads();

        // fused dt_proj + softplus: thread (lt,lj) -> dt[timestep lt, channel lj]
        {
            float v = dtb_j;
#pragma unroll
            for (int r = 0; r < 16; r++)
                v = fmaf(sx[lt * 48 + r], sdtw[r][lj], v);
            sdt_[lt][lj] = (v > 20.f) ? v : log1pf(__expf(v));
        }

        if (l0 + TCH < SEQ) {   // prefetch next chunk (overlaps compute below)
            const float* xrow = g_xdbl + (base + l0 + TCH) * 48;
            p_x0 = xrow[tid]; p_x1 = xrow[tid + 256]; p_x2 = xrow[tid + 512];
            size_t n = base + l0 + TCH + lt;
            p_u = g_u[n * DI + d0 + lj];
            p_z = g_xz[n * (2 * DI) + DI + d0 + lj];
        }
        __syncthreads();   // sdt_ ready

#pragma unroll
        for (int t = 0; t < TCH; t++) {
            float r  = sdt_[t][half];
            float uu = su_[t][half];
            float Bv = sx[t * 48 + 16 + s];
            float Cv = sx[t * 48 + 32 + s];
            float dA = __expf(r * As);
            h = fmaf(dA, h, (r * uu) * Bv);
            float p = h * Cv;
            p += __shfl_xor_sync(0xffffffffu, p, 8);
            p += __shfl_xor_sync(0xffffffffu, p, 4);
            p += __shfl_xor_sync(0xffffffffu, p, 2);
            p += __shfl_xor_sync(0xffffffffu, p, 1);
            if (s == 0) {
                float zz = sz_[t][half];
                g_y[(base + l0 + t) * DI + d] = (p + uu * Dv) * (zz * sigmoidf_(zz));
            }
        }
    }
}

// ---------------- host orchestration --------------------------------------------
extern "C" void kernel_launch(void* const* d_in, const int* in_sizes, int n_in,
                              void* d_out, int out_size) {
    const float* x    = (const float*)d_in[0];
    const float* ln_g = (const float*)d_in[1];
    const float* ln_b = (const float*)d_in[2];
    const float* inw  = (const float*)d_in[3];   // [2,1024,256]
    const float* cw   = (const float*)d_in[4];   // [2,512,4]
    const float* cb   = (const float*)d_in[5];   // [2,512]
    const float* xpw  = (const float*)d_in[6];   // [2,48,512]
    const float* dtw  = (const float*)d_in[7];   // [2,512,16]
    const float* dtb  = (const float*)d_in[8];   // [2,512]
    const float* alog = (const float*)d_in[9];   // [2,512,16]
    const float* dp   = (const float*)d_in[10];  // [2,512]
    const float* ow   = (const float*)d_in[11];  // [2,256,512]
    const float* ls   = (const float*)d_in[12];  // [2,256]
    float* out = (float*)d_out;

    cudaFuncSetAttribute(gemm_mma<0, 64>, cudaFuncAttributeMaxDynamicSharedMemorySize, GEMM_SMEM);
    cudaFuncSetAttribute(gemm_mma<0, 48>, cudaFuncAttributeMaxDynamicSharedMemorySize, GEMM_SMEM);
    cudaFuncSetAttribute(gemm_mma<1, 64>, cudaFuncAttributeMaxDynamicSharedMemorySize, GEMM_SMEM);

    float *p_ln, *p_xz, *p_u, *p_xdbl, *p_y;
    cudaGetSymbolAddress((void**)&p_ln,   g_ln);
    cudaGetSymbolAddress((void**)&p_xz,   g_xz);
    cudaGetSymbolAddress((void**)&p_u,    g_u);
    cudaGetSymbolAddress((void**)&p_xdbl, g_xdbl);
    cudaGetSymbolAddress((void**)&p_y,    g_y);

    for (int i = 0; i < 2; i++) {
        const float* xin = (i == 0) ? x : out;

        // 1) layernorm
        ln_kernel<<<NTOK / 8, 256>>>(xin, ln_g + i * DM, ln_b + i * DM);

        // 2) in_proj: [N,256] x [1024,256]^T -> [N,1024]   (tf32 mma, pipelined)
        gemm_mma<0, 64><<<dim3((2 * DI) / 64, NTOK / 128), 256, GEMM_SMEM>>>(
            p_ln, DM, inw + (size_t)i * 2 * DI * DM, p_xz, 2 * DI, DM, nullptr, nullptr);

        // 3) causal conv4 + bias + SiLU on u-half
        conv_silu_kernel<<<(NTOK * DI) / 256, 256>>>(cw + i * DI * 4, cb + i * DI);

        // 4) x_proj: [N,512] x [48,512]^T -> [N,48]   (tf32 mma, N padded to 64)
        gemm_mma<0, 48><<<dim3(1, NTOK / 128), 256, GEMM_SMEM>>>(
            p_u, DI, xpw + (size_t)i * 48 * DI, p_xdbl, 48, DI, nullptr, nullptr);

        // 5) selective scan with fused dt_proj + D skip + z gating
        scan_kernel<<<(BATCH * DI) / 16, 256>>>(
            alog + (size_t)i * DI * DS, dp + i * DI,
            dtw + (size_t)i * DI * 16, dtb + i * DI);

        // 6) out_proj fused with residual + layer_scale: out = xin + ls * (y @ ow^T)
        gemm_mma<1, 64><<<dim3(DM / 64, NTOK / 128), 256, GEMM_SMEM>>>(
            p_y, DI, ow + (size_t)i * DM * DI, out, DM, DI, xin, ls + i * DM);
    }
}

// round 9
// speedup vs baseline: 4.0348x; 1.0164x over previous
#include <cuda_runtime.h>
#include <stdint.h>
#include <math.h>

#define NTOK  16384
#define BATCH 8
#define SEQ   2048
#define DM    256
#define DI    512
#define DS    16

// ---------------- scratch (allocation-free: __device__ globals) ----------------
__device__ float g_ln[NTOK * DM];        // layernorm output
__device__ float g_xz[NTOK * 2 * DI];    // in_proj output (u | z)
__device__ float g_u[NTOK * DI];         // conv+silu output
__device__ float g_xdbl[NTOK * 48];      // x_proj output (dt_r | B | C)
__device__ float g_y[NTOK * DI];         // scan output, gated

__device__ __forceinline__ float sigmoidf_(float v) { return 1.f / (1.f + __expf(-v)); }

__device__ __forceinline__ unsigned smem_u32(const void* p) {
    return (unsigned)__cvta_generic_to_shared(p);
}
__device__ __forceinline__ void cp16(unsigned dst, const float* src) {
    asm volatile("cp.async.cg.shared.global [%0], [%1], 16;" :: "r"(dst), "l"(src));
}

// ---------------- layernorm: one warp per token (256 feats, 8/lane) ------------
__global__ void ln_kernel(const float* __restrict__ x,
                          const float* __restrict__ g,
                          const float* __restrict__ b) {
    int warp = threadIdx.x >> 5, lane = threadIdx.x & 31;
    int tok = blockIdx.x * 8 + warp;
    const float* row = x + (size_t)tok * DM;
    float v[8];
    float s = 0.f, s2 = 0.f;
#pragma unroll
    for (int i = 0; i < 8; i++) {
        v[i] = row[lane + i * 32];
        s += v[i];
        s2 += v[i] * v[i];
    }
#pragma unroll
    for (int o = 16; o; o >>= 1) {
        s  += __shfl_xor_sync(0xffffffffu, s, o);
        s2 += __shfl_xor_sync(0xffffffffu, s2, o);
    }
    float m   = s * (1.f / DM);
    float var = s2 * (1.f / DM) - m * m;
    float inv = rsqrtf(var + 1e-5f);
    float* o = g_ln + (size_t)tok * DM;
#pragma unroll
    for (int i = 0; i < 8; i++) {
        int c = lane + i * 32;
        o[c] = (v[i] - m) * inv * g[c] + b[c];
    }
}

// ============ BIG TF32 GEMM: 128x128x32 tile, 3-stage cp.async ==================
// C[M,N] = A[M,K] * W[N,K]^T.  8 warps, warp tile 64x32 (4 m-frags x 4 n-frags).
// EPI: 0 = plain store, 1 = res + ls[n]*acc
#define B_STR  36
#define B_ABUF (128 * B_STR)
#define B_STAGE (2 * B_ABUF)
#define GEMM2_SMEM (3 * B_STAGE * 4)

template <int EPI>
__global__ __launch_bounds__(256)
void gemm_big(const float* __restrict__ A, int lda,
              const float* __restrict__ W,
              float* __restrict__ C,
              int N, int K,
              const float* __restrict__ res,
              const float* __restrict__ ls) {
    extern __shared__ float dyn[];

    const int tid = threadIdx.x;
    const int warp = tid >> 5, lane = tid & 31;
    const int wm = (warp >> 2) * 64;          // 2 warp rows
    const int wn = (warp & 3) * 32;           // 4 warp cols
    const int m0 = blockIdx.y * 128, n0 = blockIdx.x * 128;
    const int lq = lane >> 2, lp = lane & 3;

    auto issue_tile = [&](int st, int k0) {
        float* As = dyn + st * B_STAGE;
        float* Ws = As + B_ABUF;
#pragma unroll
        for (int t = 0; t < 4; t++) {
            int fidx = tid + t * 256;
            int m = fidx >> 3, kc = fidx & 7;
            cp16(smem_u32(&As[m * B_STR + kc * 4]),
                 &A[(size_t)(m0 + m) * lda + k0 + kc * 4]);
        }
#pragma unroll
        for (int t = 0; t < 4; t++) {
            int fidx = tid + t * 256;
            int n = fidx >> 3, kc = fidx & 7;
            cp16(smem_u32(&Ws[n * B_STR + kc * 4]),
                 &W[(size_t)(n0 + n) * K + k0 + kc * 4]);
        }
        asm volatile("cp.async.commit_group;");
    };

    float acc[4][4][4];
#pragma unroll
    for (int i = 0; i < 4; i++)
#pragma unroll
        for (int j = 0; j < 4; j++)
#pragma unroll
            for (int q = 0; q < 4; q++) acc[i][j][q] = 0.f;

    const int nit = K / 32;
    issue_tile(0, 0);
    if (nit > 1) issue_tile(1, 32);

    for (int it = 0; it < nit; it++) {
        if (it + 1 < nit) asm volatile("cp.async.wait_group 1;");
        else              asm volatile("cp.async.wait_group 0;");
        __syncthreads();
        if (it + 2 < nit) issue_tile((it + 2) % 3, (it + 2) * 32);

        const float* ab = dyn + (it % 3) * B_STAGE;
        const float* wb = ab + B_ABUF;
#pragma unroll
        for (int kk = 0; kk < 4; kk++) {
            const int kb = kk * 8;
            unsigned int a[4][4], b[4][2];
#pragma unroll
            for (int mf = 0; mf < 4; mf++) {
                int r = wm + mf * 16 + lq;
                a[mf][0] = __float_as_uint(ab[r * B_STR + kb + lp]);
                a[mf][1] = __float_as_uint(ab[(r + 8) * B_STR + kb + lp]);
                a[mf][2] = __float_as_uint(ab[r * B_STR + kb + 4 + lp]);
                a[mf][3] = __float_as_uint(ab[(r + 8) * B_STR + kb + 4 + lp]);
            }
#pragma unroll
            for (int nf = 0; nf < 4; nf++) {
                int n = wn + nf * 8 + lq;
                b[nf][0] = __float_as_uint(wb[n * B_STR + kb + lp]);
                b[nf][1] = __float_as_uint(wb[n * B_STR + kb + 4 + lp]);
            }
#pragma unroll
            for (int mf = 0; mf < 4; mf++)
#pragma unroll
                for (int nf = 0; nf < 4; nf++) {
                    asm volatile(
                        "mma.sync.aligned.m16n8k8.row.col.f32.tf32.tf32.f32 "
                        "{%0,%1,%2,%3},{%4,%5,%6,%7},{%8,%9},{%0,%1,%2,%3};"
                        : "+f"(acc[mf][nf][0]), "+f"(acc[mf][nf][1]),
                          "+f"(acc[mf][nf][2]), "+f"(acc[mf][nf][3])
                        : "r"(a[mf][0]), "r"(a[mf][1]), "r"(a[mf][2]), "r"(a[mf][3]),
                          "r"(b[nf][0]), "r"(b[nf][1]));
                }
        }
        __syncthreads();
    }

#pragma unroll
    for (int mf = 0; mf < 4; mf++) {
#pragma unroll
        for (int nf = 0; nf < 4; nf++) {
            int r0 = m0 + wm + mf * 16 + lq;
            int c0 = n0 + wn + nf * 8 + lp * 2;
            float2 v0 = make_float2(acc[mf][nf][0], acc[mf][nf][1]);
            float2 v1 = make_float2(acc[mf][nf][2], acc[mf][nf][3]);
            if (EPI == 1) {
                float2 r0v = *(const float2*)&res[(size_t)r0 * N + c0];
                float2 r1v = *(const float2*)&res[(size_t)(r0 + 8) * N + c0];
                float l0 = ls[c0], l1 = ls[c0 + 1];
                v0.x = r0v.x + l0 * v0.x; v0.y = r0v.y + l1 * v0.y;
                v1.x = r1v.x + l0 * v1.x; v1.y = r1v.y + l1 * v1.y;
            }
            *(float2*)&C[(size_t)r0 * N + c0] = v0;
            *(float2*)&C[(size_t)(r0 + 8) * N + c0] = v1;
        }
    }
}

// ============ narrow TF32 GEMM (x_proj): 128x64x32, double-buffered =============
#define AS_STR 36
#define AS_BUF (128 * AS_STR)
#define WS_BUF (64 * AS_STR)
#define GEMM_SMEM ((2 * AS_BUF + 2 * WS_BUF) * 4)

template <int NVALID>
__global__ __launch_bounds__(256)
void gemm_mma(const float* __restrict__ A, int lda,
              const float* __restrict__ W,
              float* __restrict__ C,
              int N, int K) {
    extern __shared__ float dyn[];
    float* As = dyn;                    // [2][128][36]
    float* Ws = dyn + 2 * AS_BUF;       // [2][64][36]

    const int tid = threadIdx.x;
    const int warp = tid >> 5, lane = tid & 31;
    const int wm = (warp >> 1) * 32;
    const int wn = (warp & 1) * 32;
    const int m0 = blockIdx.y * 128, n0 = blockIdx.x * 64;
    const int lq = lane >> 2, lp = lane & 3;

    if (NVALID < 64) {
        for (int i = tid; i < 2 * WS_BUF; i += 256) {
            int row = (i % WS_BUF) / AS_STR;
            if (row >= NVALID) Ws[i] = 0.f;
        }
    }

    auto issue_tile = [&](int buf, int k0) {
#pragma unroll
        for (int t = 0; t < 4; t++) {
            int fidx = tid + t * 256;
            int m = fidx >> 3, kc = fidx & 7;
            cp16(smem_u32(&As[buf * AS_BUF + m * AS_STR + kc * 4]),
                 &A[(size_t)(m0 + m) * lda + k0 + kc * 4]);
        }
#pragma unroll
        for (int t = 0; t < 2; t++) {
            int fidx = tid + t * 256;
            int n = fidx >> 3, kc = fidx & 7;
            if (NVALID == 64 || n < NVALID)
                cp16(smem_u32(&Ws[buf * WS_BUF + n * AS_STR + kc * 4]),
                     &W[(size_t)(n0 + n) * K + k0 + kc * 4]);
        }
        asm volatile("cp.async.commit_group;");
    };

    float acc[2][4][4];
#pragma unroll
    for (int i = 0; i < 2; i++)
#pragma unroll
        for (int j = 0; j < 4; j++)
#pragma unroll
            for (int q = 0; q < 4; q++) acc[i][j][q] = 0.f;

    const int nit = K / 32;
    issue_tile(0, 0);

    for (int it = 0; it < nit; it++) {
        int buf = it & 1;
        if (it + 1 < nit) {
            issue_tile(buf ^ 1, (it + 1) * 32);
            asm volatile("cp.async.wait_group 1;");
        } else {
            asm volatile("cp.async.wait_group 0;");
        }
        __syncthreads();

        const float* ab = As + buf * AS_BUF;
        const float* wb = Ws + buf * WS_BUF;
#pragma unroll
        for (int kk = 0; kk < 4; kk++) {
            const int kb = kk * 8;
            unsigned int a[2][4], b[4][2];
#pragma unroll
            for (int mf = 0; mf < 2; mf++) {
                int r = wm + mf * 16 + lq;
                a[mf][0] = __float_as_uint(ab[r * AS_STR + kb + lp]);
                a[mf][1] = __float_as_uint(ab[(r + 8) * AS_STR + kb + lp]);
                a[mf][2] = __float_as_uint(ab[r * AS_STR + kb + 4 + lp]);
                a[mf][3] = __float_as_uint(ab[(r + 8) * AS_STR + kb + 4 + lp]);
            }
#pragma unroll
            for (int nf = 0; nf < 4; nf++) {
                int n = wn + nf * 8 + lq;
                b[nf][0] = __float_as_uint(wb[n * AS_STR + kb + lp]);
                b[nf][1] = __float_as_uint(wb[n * AS_STR + kb + 4 + lp]);
            }
#pragma unroll
            for (int mf = 0; mf < 2; mf++)
#pragma unroll
                for (int nf = 0; nf < 4; nf++) {
                    asm volatile(
                        "mma.sync.aligned.m16n8k8.row.col.f32.tf32.tf32.f32 "
                        "{%0,%1,%2,%3},{%4,%5,%6,%7},{%8,%9},{%0,%1,%2,%3};"
                        : "+f"(acc[mf][nf][0]), "+f"(acc[mf][nf][1]),
                          "+f"(acc[mf][nf][2]), "+f"(acc[mf][nf][3])
                        : "r"(a[mf][0]), "r"(a[mf][1]), "r"(a[mf][2]), "r"(a[mf][3]),
                          "r"(b[nf][0]), "r"(b[nf][1]));
                }
        }
        __syncthreads();
    }

#pragma unroll
    for (int mf = 0; mf < 2; mf++) {
#pragma unroll
        for (int nf = 0; nf < 4; nf++) {
            int r0 = m0 + wm + mf * 16 + lq;
            int c0 = n0 + wn + nf * 8 + lp * 2;
            if (NVALID < 64 && c0 >= NVALID) continue;
            float2 v0 = make_float2(acc[mf][nf][0], acc[mf][nf][1]);
            float2 v1 = make_float2(acc[mf][nf][2], acc[mf][nf][3]);
            *(float2*)&C[(size_t)r0 * N + c0] = v0;
            *(float2*)&C[(size_t)(r0 + 8) * N + c0] = v1;
        }
    }
}

// ---------------- causal depthwise conv(4) + bias + SiLU ------------------------
__global__ void conv_silu_kernel(const float* __restrict__ cw,
                                 const float* __restrict__ cb) {
    int idx = blockIdx.x * blockDim.x + threadIdx.x;  // over NTOK*DI
    int d = idx & (DI - 1);
    int n = idx >> 9;         // token index (b*SEQ + l)
    int l = n & (SEQ - 1);
    float acc = cb[d];
    const float* w = cw + d * 4;
#pragma unroll
    for (int j = 0; j < 4; j++) {
        int ll = l - 3 + j;
        if (ll >= 0) acc = fmaf(w[j], g_xz[(size_t)(n - 3 + j) * (2 * DI) + d], acc);
    }
    g_u[idx] = acc * sigmoidf_(acc);
}

// ---------------- selective scan with fused dt_proj+softplus --------------------
#define TCH 16
__global__ __launch_bounds__(256)
void scan_kernel(const float* __restrict__ A_log,
                 const float* __restrict__ Dp,
                 const float* __restrict__ dtw,   // [DI,16]
                 const float* __restrict__ dtb) { // [DI]
    __shared__ float sx[TCH * 48];       // xdbl rows for the chunk
    __shared__ float su_[TCH][16], sz_[TCH][16];
    __shared__ float sdtw[16][17];       // [r][j] : dtw[(d0+j)*16 + r]
    __shared__ float sdt_[TCH][16];

    int tid = threadIdx.x;
    int half = tid >> 4;              // channel within block (0..15)
    int s = tid & 15;                 // state index
    int b = blockIdx.x >> 5;          // 32 blocks per batch (512/16)
    int d0 = (blockIdx.x & 31) << 4;
    int d = d0 + half;

    int lt = tid >> 4, lj = tid & 15; // loading/compute role: (timestep, channel)

    {
        int j = tid >> 4, r = tid & 15;
        sdtw[r][j] = dtw[(d0 + j) * 16 + r];
    }
    float dtb_j = dtb[d0 + lj];

    float As = -__expf(A_log[d * DS + s]);
    float Dv = Dp[d];
    float h = 0.f;
    size_t base = (size_t)b * SEQ;

    float p_x0, p_x1, p_x2, p_u, p_z;
    {
        const float* xrow = g_xdbl + base * 48;
        p_x0 = xrow[tid]; p_x1 = xrow[tid + 256]; p_x2 = xrow[tid + 512];
        size_t n = base + lt;
        p_u = g_u[n * DI + d0 + lj];
        p_z = g_xz[n * (2 * DI) + DI + d0 + lj];
    }

    for (int l0 = 0; l0 < SEQ; l0 += TCH) {
        __syncthreads();
        sx[tid] = p_x0; sx[tid + 256] = p_x1; sx[tid + 512] = p_x2;
        su_[lt][lj] = p_u; sz_[lt][lj] = p_z;
        __syncthreads();

        {
            float v = dtb_j;
#pragma unroll
            for (int r = 0; r < 16; r++)
                v = fmaf(sx[lt * 48 + r], sdtw[r][lj], v);
            sdt_[lt][lj] = (v > 20.f) ? v : log1pf(__expf(v));
        }

        if (l0 + TCH < SEQ) {
            const float* xrow = g_xdbl + (base + l0 + TCH) * 48;
            p_x0 = xrow[tid]; p_x1 = xrow[tid + 256]; p_x2 = xrow[tid + 512];
            size_t n = base + l0 + TCH + lt;
            p_u = g_u[n * DI + d0 + lj];
            p_z = g_xz[n * (2 * DI) + DI + d0 + lj];
        }
        __syncthreads();

#pragma unroll
        for (int t = 0; t < TCH; t++) {
            float r  = sdt_[t][half];
            float uu = su_[t][half];
            float Bv = sx[t * 48 + 16 + s];
            float Cv = sx[t * 48 + 32 + s];
            float dA = __expf(r * As);
            h = fmaf(dA, h, (r * uu) * Bv);
            float p = h * Cv;
            p += __shfl_xor_sync(0xffffffffu, p, 8);
            p += __shfl_xor_sync(0xffffffffu, p, 4);
            p += __shfl_xor_sync(0xffffffffu, p, 2);
            p += __shfl_xor_sync(0xffffffffu, p, 1);
            if (s == 0) {
                float zz = sz_[t][half];
                g_y[(base + l0 + t) * DI + d] = (p + uu * Dv) * (zz * sigmoidf_(zz));
            }
        }
    }
}

// ---------------- host orchestration --------------------------------------------
extern "C" void kernel_launch(void* const* d_in, const int* in_sizes, int n_in,
                              void* d_out, int out_size) {
    const float* x    = (const float*)d_in[0];
    const float* ln_g = (const float*)d_in[1];
    const float* ln_b = (const float*)d_in[2];
    const float* inw  = (const float*)d_in[3];   // [2,1024,256]
    const float* cw   = (const float*)d_in[4];   // [2,512,4]
    const float* cb   = (const float*)d_in[5];   // [2,512]
    const float* xpw  = (const float*)d_in[6];   // [2,48,512]
    const float* dtw  = (const float*)d_in[7];   // [2,512,16]
    const float* dtb  = (const float*)d_in[8];   // [2,512]
    const float* alog = (const float*)d_in[9];   // [2,512,16]
    const float* dp   = (const float*)d_in[10];  // [2,512]
    const float* ow   = (const float*)d_in[11];  // [2,256,512]
    const float* ls   = (const float*)d_in[12];  // [2,256]
    float* out = (float*)d_out;

    cudaFuncSetAttribute(gemm_big<0>, cudaFuncAttributeMaxDynamicSharedMemorySize, GEMM2_SMEM);
    cudaFuncSetAttribute(gemm_big<1>, cudaFuncAttributeMaxDynamicSharedMemorySize, GEMM2_SMEM);
    cudaFuncSetAttribute(gemm_mma<48>, cudaFuncAttributeMaxDynamicSharedMemorySize, GEMM_SMEM);

    float *p_ln, *p_xz, *p_u, *p_xdbl, *p_y;
    cudaGetSymbolAddress((void**)&p_ln,   g_ln);
    cudaGetSymbolAddress((void**)&p_xz,   g_xz);
    cudaGetSymbolAddress((void**)&p_u,    g_u);
    cudaGetSymbolAddress((void**)&p_xdbl, g_xdbl);
    cudaGetSymbolAddress((void**)&p_y,    g_y);

    for (int i = 0; i < 2; i++) {
        const float* xin = (i == 0) ? x : out;

        // 1) layernorm
        ln_kernel<<<NTOK / 8, 256>>>(xin, ln_g + i * DM, ln_b + i * DM);

        // 2) in_proj: [N,256] x [1024,256]^T -> [N,1024]   (tf32, 3-stage pipeline)
        gemm_big<0><<<dim3((2 * DI) / 128, NTOK / 128), 256, GEMM2_SMEM>>>(
            p_ln, DM, inw + (size_t)i * 2 * DI * DM, p_xz, 2 * DI, DM, nullptr, nullptr);

        // 3) causal conv4 + bias + SiLU on u-half
        conv_silu_kernel<<<(NTOK * DI) / 256, 256>>>(cw + i * DI * 4, cb + i * DI);

        // 4) x_proj: [N,512] x [48,512]^T -> [N,48]   (tf32 mma, N padded to 64)
        gemm_mma<48><<<dim3(1, NTOK / 128), 256, GEMM_SMEM>>>(
            p_u, DI, xpw + (size_t)i * 48 * DI, p_xdbl, 48, DI);

        // 5) selective scan with fused dt_proj + D skip + z gating
        scan_kernel<<<(BATCH * DI) / 16, 256>>>(
            alog + (size_t)i * DI * DS, dp + i * DI,
            dtw + (size_t)i * DI * 16, dtb + i * DI);

        // 6) out_proj fused with residual + layer_scale: out = xin + ls * (y @ ow^T)
        gemm_big<1><<<dim3(DM / 128, NTOK / 128), 256, GEMM2_SMEM>>>(
            p_y, DI, ow + (size_t)i * DM * DI, out, DM, DI, xin, ls + i * DM);
    }
}

// round 10
// speedup vs baseline: 7.3485x; 1.8213x over previous
#include <cuda_runtime.h>
#include <stdint.h>
#include <math.h>

#define NTOK  16384
#define BATCH 8
#define SEQ   2048
#define DM    256
#define DI    512
#define DS    16

// ---------------- scratch (allocation-free: __device__ globals) ----------------
__device__ float g_ln[NTOK * DM];        // layernorm output
__device__ float g_xz[NTOK * 2 * DI];    // in_proj output (u | z)
__device__ float g_u[NTOK * DI];         // conv+silu output
__device__ float g_xdbl[NTOK * 48];      // x_proj output (dt_r | B | C)
__device__ float g_y[NTOK * DI];         // scan output, gated

__device__ __forceinline__ float sigmoidf_(float v) { return 1.f / (1.f + __expf(-v)); }

__device__ __forceinline__ unsigned smem_u32(const void* p) {
    return (unsigned)__cvta_generic_to_shared(p);
}
__device__ __forceinline__ void cp16(unsigned dst, const float* src) {
    asm volatile("cp.async.cg.shared.global [%0], [%1], 16;" :: "r"(dst), "l"(src));
}

// ---------------- layernorm: one warp per token (256 feats, 8/lane) ------------
__global__ void ln_kernel(const float* __restrict__ x,
                          const float* __restrict__ g,
                          const float* __restrict__ b) {
    int warp = threadIdx.x >> 5, lane = threadIdx.x & 31;
    int tok = blockIdx.x * 8 + warp;
    const float* row = x + (size_t)tok * DM;
    float v[8];
    float s = 0.f, s2 = 0.f;
#pragma unroll
    for (int i = 0; i < 8; i++) {
        v[i] = row[lane + i * 32];
        s += v[i];
        s2 += v[i] * v[i];
    }
#pragma unroll
    for (int o = 16; o; o >>= 1) {
        s  += __shfl_xor_sync(0xffffffffu, s, o);
        s2 += __shfl_xor_sync(0xffffffffu, s2, o);
    }
    float m   = s * (1.f / DM);
    float var = s2 * (1.f / DM) - m * m;
    float inv = rsqrtf(var + 1e-5f);
    float* o = g_ln + (size_t)tok * DM;
#pragma unroll
    for (int i = 0; i < 8; i++) {
        int c = lane + i * 32;
        o[c] = (v[i] - m) * inv * g[c] + b[c];
    }
}

// ============ BIG TF32 GEMM: 128x128x32 tile, 3-stage cp.async ==================
#define B_STR  36
#define B_ABUF (128 * B_STR)
#define B_STAGE (2 * B_ABUF)
#define GEMM2_SMEM (3 * B_STAGE * 4)

template <int EPI>
__global__ __launch_bounds__(256)
void gemm_big(const float* __restrict__ A, int lda,
              const float* __restrict__ W,
              float* __restrict__ C,
              int N, int K,
              const float* __restrict__ res,
              const float* __restrict__ ls) {
    extern __shared__ float dyn[];

    const int tid = threadIdx.x;
    const int warp = tid >> 5, lane = tid & 31;
    const int wm = (warp >> 2) * 64;
    const int wn = (warp & 3) * 32;
    const int m0 = blockIdx.y * 128, n0 = blockIdx.x * 128;
    const int lq = lane >> 2, lp = lane & 3;

    auto issue_tile = [&](int st, int k0) {
        float* As = dyn + st * B_STAGE;
        float* Ws = As + B_ABUF;
#pragma unroll
        for (int t = 0; t < 4; t++) {
            int fidx = tid + t * 256;
            int m = fidx >> 3, kc = fidx & 7;
            cp16(smem_u32(&As[m * B_STR + kc * 4]),
                 &A[(size_t)(m0 + m) * lda + k0 + kc * 4]);
        }
#pragma unroll
        for (int t = 0; t < 4; t++) {
            int fidx = tid + t * 256;
            int n = fidx >> 3, kc = fidx & 7;
            cp16(smem_u32(&Ws[n * B_STR + kc * 4]),
                 &W[(size_t)(n0 + n) * K + k0 + kc * 4]);
        }
        asm volatile("cp.async.commit_group;");
    };

    float acc[4][4][4];
#pragma unroll
    for (int i = 0; i < 4; i++)
#pragma unroll
        for (int j = 0; j < 4; j++)
#pragma unroll
            for (int q = 0; q < 4; q++) acc[i][j][q] = 0.f;

    const int nit = K / 32;
    issue_tile(0, 0);
    if (nit > 1) issue_tile(1, 32);

    for (int it = 0; it < nit; it++) {
        if (it + 1 < nit) asm volatile("cp.async.wait_group 1;");
        else              asm volatile("cp.async.wait_group 0;");
        __syncthreads();
        if (it + 2 < nit) issue_tile((it + 2) % 3, (it + 2) * 32);

        const float* ab = dyn + (it % 3) * B_STAGE;
        const float* wb = ab + B_ABUF;
#pragma unroll
        for (int kk = 0; kk < 4; kk++) {
            const int kb = kk * 8;
            unsigned int a[4][4], b[4][2];
#pragma unroll
            for (int mf = 0; mf < 4; mf++) {
                int r = wm + mf * 16 + lq;
                a[mf][0] = __float_as_uint(ab[r * B_STR + kb + lp]);
                a[mf][1] = __float_as_uint(ab[(r + 8) * B_STR + kb + lp]);
                a[mf][2] = __float_as_uint(ab[r * B_STR + kb + 4 + lp]);
                a[mf][3] = __float_as_uint(ab[(r + 8) * B_STR + kb + 4 + lp]);
            }
#pragma unroll
            for (int nf = 0; nf < 4; nf++) {
                int n = wn + nf * 8 + lq;
                b[nf][0] = __float_as_uint(wb[n * B_STR + kb + lp]);
                b[nf][1] = __float_as_uint(wb[n * B_STR + kb + 4 + lp]);
            }
#pragma unroll
            for (int mf = 0; mf < 4; mf++)
#pragma unroll
                for (int nf = 0; nf < 4; nf++) {
                    asm volatile(
                        "mma.sync.aligned.m16n8k8.row.col.f32.tf32.tf32.f32 "
                        "{%0,%1,%2,%3},{%4,%5,%6,%7},{%8,%9},{%0,%1,%2,%3};"
                        : "+f"(acc[mf][nf][0]), "+f"(acc[mf][nf][1]),
                          "+f"(acc[mf][nf][2]), "+f"(acc[mf][nf][3])
                        : "r"(a[mf][0]), "r"(a[mf][1]), "r"(a[mf][2]), "r"(a[mf][3]),
                          "r"(b[nf][0]), "r"(b[nf][1]));
                }
        }
        __syncthreads();
    }

#pragma unroll
    for (int mf = 0; mf < 4; mf++) {
#pragma unroll
        for (int nf = 0; nf < 4; nf++) {
            int r0 = m0 + wm + mf * 16 + lq;
            int c0 = n0 + wn + nf * 8 + lp * 2;
            float2 v0 = make_float2(acc[mf][nf][0], acc[mf][nf][1]);
            float2 v1 = make_float2(acc[mf][nf][2], acc[mf][nf][3]);
            if (EPI == 1) {
                float2 r0v = *(const float2*)&res[(size_t)r0 * N + c0];
                float2 r1v = *(const float2*)&res[(size_t)(r0 + 8) * N + c0];
                float l0 = ls[c0], l1 = ls[c0 + 1];
                v0.x = r0v.x + l0 * v0.x; v0.y = r0v.y + l1 * v0.y;
                v1.x = r1v.x + l0 * v1.x; v1.y = r1v.y + l1 * v1.y;
            }
            *(float2*)&C[(size_t)r0 * N + c0] = v0;
            *(float2*)&C[(size_t)(r0 + 8) * N + c0] = v1;
        }
    }
}

// ============ narrow TF32 GEMM (x_proj): 128x64x32, double-buffered =============
#define AS_STR 36
#define AS_BUF (128 * AS_STR)
#define WS_BUF (64 * AS_STR)
#define GEMM_SMEM ((2 * AS_BUF + 2 * WS_BUF) * 4)

template <int NVALID>
__global__ __launch_bounds__(256)
void gemm_mma(const float* __restrict__ A, int lda,
              const float* __restrict__ W,
              float* __restrict__ C,
              int N, int K) {
    extern __shared__ float dyn[];
    float* As = dyn;
    float* Ws = dyn + 2 * AS_BUF;

    const int tid = threadIdx.x;
    const int warp = tid >> 5, lane = tid & 31;
    const int wm = (warp >> 1) * 32;
    const int wn = (warp & 1) * 32;
    const int m0 = blockIdx.y * 128, n0 = blockIdx.x * 64;
    const int lq = lane >> 2, lp = lane & 3;

    if (NVALID < 64) {
        for (int i = tid; i < 2 * WS_BUF; i += 256) {
            int row = (i % WS_BUF) / AS_STR;
            if (row >= NVALID) Ws[i] = 0.f;
        }
    }

    auto issue_tile = [&](int buf, int k0) {
#pragma unroll
        for (int t = 0; t < 4; t++) {
            int fidx = tid + t * 256;
            int m = fidx >> 3, kc = fidx & 7;
            cp16(smem_u32(&As[buf * AS_BUF + m * AS_STR + kc * 4]),
                 &A[(size_t)(m0 + m) * lda + k0 + kc * 4]);
        }
#pragma unroll
        for (int t = 0; t < 2; t++) {
            int fidx = tid + t * 256;
            int n = fidx >> 3, kc = fidx & 7;
            if (NVALID == 64 || n < NVALID)
                cp16(smem_u32(&Ws[buf * WS_BUF + n * AS_STR + kc * 4]),
                     &W[(size_t)(n0 + n) * K + k0 + kc * 4]);
        }
        asm volatile("cp.async.commit_group;");
    };

    float acc[2][4][4];
#pragma unroll
    for (int i = 0; i < 2; i++)
#pragma unroll
        for (int j = 0; j < 4; j++)
#pragma unroll
            for (int q = 0; q < 4; q++) acc[i][j][q] = 0.f;

    const int nit = K / 32;
    issue_tile(0, 0);

    for (int it = 0; it < nit; it++) {
        int buf = it & 1;
        if (it + 1 < nit) {
            issue_tile(buf ^ 1, (it + 1) * 32);
            asm volatile("cp.async.wait_group 1;");
        } else {
            asm volatile("cp.async.wait_group 0;");
        }
        __syncthreads();

        const float* ab = As + buf * AS_BUF;
        const float* wb = Ws + buf * WS_BUF;
#pragma unroll
        for (int kk = 0; kk < 4; kk++) {
            const int kb = kk * 8;
            unsigned int a[2][4], b[4][2];
#pragma unroll
            for (int mf = 0; mf < 2; mf++) {
                int r = wm + mf * 16 + lq;
                a[mf][0] = __float_as_uint(ab[r * AS_STR + kb + lp]);
                a[mf][1] = __float_as_uint(ab[(r + 8) * AS_STR + kb + lp]);
                a[mf][2] = __float_as_uint(ab[r * AS_STR + kb + 4 + lp]);
                a[mf][3] = __float_as_uint(ab[(r + 8) * AS_STR + kb + 4 + lp]);
            }
#pragma unroll
            for (int nf = 0; nf < 4; nf++) {
                int n = wn + nf * 8 + lq;
                b[nf][0] = __float_as_uint(wb[n * AS_STR + kb + lp]);
                b[nf][1] = __float_as_uint(wb[n * AS_STR + kb + 4 + lp]);
            }
#pragma unroll
            for (int mf = 0; mf < 2; mf++)
#pragma unroll
                for (int nf = 0; nf < 4; nf++) {
                    asm volatile(
                        "mma.sync.aligned.m16n8k8.row.col.f32.tf32.tf32.f32 "
                        "{%0,%1,%2,%3},{%4,%5,%6,%7},{%8,%9},{%0,%1,%2,%3};"
                        : "+f"(acc[mf][nf][0]), "+f"(acc[mf][nf][1]),
                          "+f"(acc[mf][nf][2]), "+f"(acc[mf][nf][3])
                        : "r"(a[mf][0]), "r"(a[mf][1]), "r"(a[mf][2]), "r"(a[mf][3]),
                          "r"(b[nf][0]), "r"(b[nf][1]));
                }
        }
        __syncthreads();
    }

#pragma unroll
    for (int mf = 0; mf < 2; mf++) {
#pragma unroll
        for (int nf = 0; nf < 4; nf++) {
            int r0 = m0 + wm + mf * 16 + lq;
            int c0 = n0 + wn + nf * 8 + lp * 2;
            if (NVALID < 64 && c0 >= NVALID) continue;
            float2 v0 = make_float2(acc[mf][nf][0], acc[mf][nf][1]);
            float2 v1 = make_float2(acc[mf][nf][2], acc[mf][nf][3]);
            *(float2*)&C[(size_t)r0 * N + c0] = v0;
            *(float2*)&C[(size_t)(r0 + 8) * N + c0] = v1;
        }
    }
}

// ---------------- causal depthwise conv(4) + bias + SiLU ------------------------
__global__ void conv_silu_kernel(const float* __restrict__ cw,
                                 const float* __restrict__ cb) {
    int idx = blockIdx.x * blockDim.x + threadIdx.x;  // over NTOK*DI
    int d = idx & (DI - 1);
    int n = idx >> 9;         // token index (b*SEQ + l)
    int l = n & (SEQ - 1);
    float acc = cb[d];
    const float* w = cw + d * 4;
#pragma unroll
    for (int j = 0; j < 4; j++) {
        int ll = l - 3 + j;
        if (ll >= 0) acc = fmaf(w[j], g_xz[(size_t)(n - 3 + j) * (2 * DI) + d], acc);
    }
    g_u[idx] = acc * sigmoidf_(acc);
}

// ---------------- selective scan: shuffle-free two-phase reduction --------------
// block = 256 threads = 16 channels x 16 states.  Per 16-step chunk:
//   phase 1: h-recurrence only (chain = 16 FMAs; exps independent -> ILP),
//            p_t = h_t * C_t buffered in registers.
//   phase 2: warp-local smem transpose (stride 33, conflict-free), each lane
//            sums one timestep's 16 states with plain FADDs. No shuffles.
#define TCH 16
__global__ __launch_bounds__(256)
void scan_kernel(const float* __restrict__ A_log,
                 const float* __restrict__ Dp,
                 const float* __restrict__ dtw,   // [DI,16]
                 const float* __restrict__ dtb) { // [DI]
    __shared__ float sx[TCH * 48];        // xdbl rows for the chunk
    __shared__ float su_[TCH][17], sz_[TCH][17], sdt_[TCH][17];
    __shared__ float sdtw[16][17];        // [r][j] : dtw[(d0+j)*16 + r]
    __shared__ float sp[8][TCH][33];      // per-warp p transpose buffer

    int tid = threadIdx.x;
    int half = tid >> 4;              // channel within block (0..15)
    int s = tid & 15;                 // state index
    int w = tid >> 5;                 // warp (covers channels 2w, 2w+1)
    int lane = tid & 31;
    int b = blockIdx.x >> 5;          // 32 blocks per batch (512/16)
    int d0 = (blockIdx.x & 31) << 4;
    int d = d0 + half;

    int lt = tid >> 4, lj = tid & 15; // staging role: (timestep, channel/state)

    sdtw[s][half] = dtw[(d0 + half) * 16 + s];
    float dtb_j = dtb[d0 + lj];

    float As = -__expf(A_log[d * DS + s]);
    float h = 0.f;
    size_t base = (size_t)b * SEQ;

    // phase-2 role: lane -> (timestep t2, channel ch2 of this warp's two)
    int t2 = lane & 15, ch2 = lane >> 4;
    int cB = w * 2 + ch2;             // channel-in-block for phase 2
    float Dv2 = Dp[d0 + cB];

    // prefetch chunk 0
    float p_x0, p_x1, p_x2, p_u, p_z;
    {
        const float* xrow = g_xdbl + base * 48;
        p_x0 = xrow[tid]; p_x1 = xrow[tid + 256]; p_x2 = xrow[tid + 512];
        size_t n = base + lt;
        p_u = g_u[n * DI + d0 + lj];
        p_z = g_xz[n * (2 * DI) + DI + d0 + lj];
    }

    for (int l0 = 0; l0 < SEQ; l0 += TCH) {
        __syncthreads();   // previous chunk fully consumed (incl. phase-2 reads)
        sx[tid] = p_x0; sx[tid + 256] = p_x1; sx[tid + 512] = p_x2;
        su_[lt][lj] = p_u; sz_[lt][lj] = p_z;
        __syncthreads();

        // fused dt_proj + softplus: thread (lt,lj) -> dt[timestep lt, channel lj]
        {
            float v = dtb_j;
#pragma unroll
            for (int r = 0; r < 16; r++)
                v = fmaf(sx[lt * 48 + r], sdtw[r][lj], v);
            sdt_[lt][lj] = (v > 20.f) ? v : log1pf(__expf(v));
        }

        if (l0 + TCH < SEQ) {   // prefetch next chunk (overlaps compute below)
            const float* xrow = g_xdbl + (base + l0 + TCH) * 48;
            p_x0 = xrow[tid]; p_x1 = xrow[tid + 256]; p_x2 = xrow[tid + 512];
            size_t n = base + l0 + TCH + lt;
            p_u = g_u[n * DI + d0 + lj];
            p_z = g_xz[n * (2 * DI) + DI + d0 + lj];
        }
        __syncthreads();   // sdt_ ready

        // ---- phase 1: recurrence, p_t buffered ----
        float p[TCH];
#pragma unroll
        for (int t = 0; t < TCH; t++) {
            float r  = sdt_[t][half];
            float uu = su_[t][half];
            float dA = __expf(r * As);
            h = fmaf(dA, h, (r * uu) * sx[t * 48 + 16 + s]);
            p[t] = h * sx[t * 48 + 32 + s];
        }

        // ---- phase 2: warp-local transpose + sum over states ----
#pragma unroll
        for (int t = 0; t < TCH; t++) sp[w][t][lane] = p[t];
        __syncwarp();
        float acc = 0.f;
#pragma unroll
        for (int k = 0; k < 16; k++) acc += sp[w][t2][ch2 * 16 + k];

        float uu2 = su_[t2][cB];
        float zz  = sz_[t2][cB];
        g_y[(base + l0 + t2) * DI + d0 + cB] =
            (acc + uu2 * Dv2) * (zz * sigmoidf_(zz));
    }
}

// ---------------- host orchestration --------------------------------------------
extern "C" void kernel_launch(void* const* d_in, const int* in_sizes, int n_in,
                              void* d_out, int out_size) {
    const float* x    = (const float*)d_in[0];
    const float* ln_g = (const float*)d_in[1];
    const float* ln_b = (const float*)d_in[2];
    const float* inw  = (const float*)d_in[3];   // [2,1024,256]
    const float* cw   = (const float*)d_in[4];   // [2,512,4]
    const float* cb   = (const float*)d_in[5];   // [2,512]
    const float* xpw  = (const float*)d_in[6];   // [2,48,512]
    const float* dtw  = (const float*)d_in[7];   // [2,512,16]
    const float* dtb  = (const float*)d_in[8];   // [2,512]
    const float* alog = (const float*)d_in[9];   // [2,512,16]
    const float* dp   = (const float*)d_in[10];  // [2,512]
    const float* ow   = (const float*)d_in[11];  // [2,256,512]
    const float* ls   = (const float*)d_in[12];  // [2,256]
    float* out = (float*)d_out;

    cudaFuncSetAttribute(gemm_big<0>, cudaFuncAttributeMaxDynamicSharedMemorySize, GEMM2_SMEM);
    cudaFuncSetAttribute(gemm_big<1>, cudaFuncAttributeMaxDynamicSharedMemorySize, GEMM2_SMEM);
    cudaFuncSetAttribute(gemm_mma<48>, cudaFuncAttributeMaxDynamicSharedMemorySize, GEMM_SMEM);

    float *p_ln, *p_xz, *p_u, *p_xdbl, *p_y;
    cudaGetSymbolAddress((void**)&p_ln,   g_ln);
    cudaGetSymbolAddress((void**)&p_xz,   g_xz);
    cudaGetSymbolAddress((void**)&p_u,    g_u);
    cudaGetSymbolAddress((void**)&p_xdbl, g_xdbl);
    cudaGetSymbolAddress((void**)&p_y,    g_y);

    for (int i = 0; i < 2; i++) {
        const float* xin = (i == 0) ? x : out;

        // 1) layernorm
        ln_kernel<<<NTOK / 8, 256>>>(xin, ln_g + i * DM, ln_b + i * DM);

        // 2) in_proj: [N,256] x [1024,256]^T -> [N,1024]   (tf32, 3-stage pipeline)
        gemm_big<0><<<dim3((2 * DI) / 128, NTOK / 128), 256, GEMM2_SMEM>>>(
            p_ln, DM, inw + (size_t)i * 2 * DI * DM, p_xz, 2 * DI, DM, nullptr, nullptr);

        // 3) causal conv4 + bias + SiLU on u-half
        conv_silu_kernel<<<(NTOK * DI) / 256, 256>>>(cw + i * DI * 4, cb + i * DI);

        // 4) x_proj: [N,512] x [48,512]^T -> [N,48]   (tf32 mma, N padded to 64)
        gemm_mma<48><<<dim3(1, NTOK / 128), 256, GEMM_SMEM>>>(
            p_u, DI, xpw + (size_t)i * 48 * DI, p_xdbl, 48, DI);

        // 5) selective scan with fused dt_proj + D skip + z gating
        scan_kernel<<<(BATCH * DI) / 16, 256>>>(
            alog + (size_t)i * DI * DS, dp + i * DI,
            dtw + (size_t)i * DI * 16, dtb + i * DI);

        // 6) out_proj fused with residual + layer_scale: out = xin + ls * (y @ ow^T)
        gemm_big<1><<<dim3(DM / 128, NTOK / 128), 256, GEMM2_SMEM>>>(
            p_y, DI, ow + (size_t)i * DM * DI, out, DM, DI, xin, ls + i * DM);
    }
}

// round 11
// speedup vs baseline: 8.0072x; 1.0896x over previous
#include <cuda_runtime.h>
#include <cuda_bf16.h>
#include <stdint.h>
#include <math.h>

#define NTOK  16384
#define BATCH 8
#define SEQ   2048
#define DM    256
#define DI    512
#define DS    16

// weight scratch layout per layer: [inw 1024*256 | xpw 48*512 | ow 256*512]
#define W_INP_SZ (1024 * 256)
#define W_XP_OFF W_INP_SZ
#define W_XP_SZ  (48 * 512)
#define W_OW_OFF (W_XP_OFF + W_XP_SZ)
#define W_OW_SZ  (256 * 512)
#define W_LAYER  (W_OW_OFF + W_OW_SZ)

// ---------------- scratch (allocation-free: __device__ globals) ----------------
__device__ __nv_bfloat16 g_lnbf[NTOK * DM];     // layernorm output (bf16, gemm A)
__device__ float         g_xz[NTOK * 2 * DI];   // in_proj output (u | z)
__device__ float         g_u[NTOK * DI];        // conv+silu output (fp32, scan)
__device__ __nv_bfloat16 g_ubf[NTOK * DI];      // conv+silu output (bf16, gemm A)
__device__ float         g_xdbl[NTOK * 48];     // x_proj output (dt_r | B | C)
__device__ __nv_bfloat16 g_ybf[NTOK * DI];      // scan output, gated (bf16, gemm A)
__device__ __nv_bfloat16 g_wbf[2 * W_LAYER];    // bf16 weights

__device__ __forceinline__ float sigmoidf_(float v) { return 1.f / (1.f + __expf(-v)); }

__device__ __forceinline__ unsigned smem_u32(const void* p) {
    return (unsigned)__cvta_generic_to_shared(p);
}
__device__ __forceinline__ void cp16(unsigned dst, const void* src) {
    asm volatile("cp.async.cg.shared.global [%0], [%1], 16;" :: "r"(dst), "l"(src));
}

// ---------------- one-shot weight conversion fp32 -> bf16 -----------------------
__global__ void convert_weights(const float* __restrict__ inw,
                                const float* __restrict__ xpw,
                                const float* __restrict__ ow) {
    int idx = blockIdx.x * 256 + threadIdx.x;
    if (idx >= 2 * W_LAYER) return;
    int layer = idx / W_LAYER, r = idx % W_LAYER;
    float v;
    if (r < W_INP_SZ)       v = inw[(size_t)layer * W_INP_SZ + r];
    else if (r < W_OW_OFF)  v = xpw[(size_t)layer * W_XP_SZ + (r - W_XP_OFF)];
    else                    v = ow[(size_t)layer * W_OW_SZ + (r - W_OW_OFF)];
    g_wbf[idx] = __float2bfloat16(v);
}

// ---------------- layernorm: one warp per token, writes bf16 --------------------
__global__ void ln_kernel(const float* __restrict__ x,
                          const float* __restrict__ g,
                          const float* __restrict__ b) {
    int warp = threadIdx.x >> 5, lane = threadIdx.x & 31;
    int tok = blockIdx.x * 8 + warp;
    const float* row = x + (size_t)tok * DM;
    float v[8];
    float s = 0.f, s2 = 0.f;
#pragma unroll
    for (int i = 0; i < 8; i++) {
        v[i] = row[lane + i * 32];
        s += v[i];
        s2 += v[i] * v[i];
    }
#pragma unroll
    for (int o = 16; o; o >>= 1) {
        s  += __shfl_xor_sync(0xffffffffu, s, o);
        s2 += __shfl_xor_sync(0xffffffffu, s2, o);
    }
    float m   = s * (1.f / DM);
    float var = s2 * (1.f / DM) - m * m;
    float inv = rsqrtf(var + 1e-5f);
    __nv_bfloat16* o = g_lnbf + (size_t)tok * DM;
#pragma unroll
    for (int i = 0; i < 8; i++) {
        int c = lane + i * 32;
        o[c] = __float2bfloat16((v[i] - m) * inv * g[c] + b[c]);
    }
}

// ============ BIG bf16 GEMM: 128x128x32, m16n8k16, 3-stage cp.async =============
// C[M,N] = A[M,K] * W[N,K]^T, A/W bf16, C fp32.  8 warps, warp tile 64x32.
// Smem rows: 40 bf16 elems (80B); 32-bit frag loads hit all 32 banks.
#define BB_STR  40
#define BB_ABUF (128 * BB_STR)
#define BB_STAGE (2 * BB_ABUF)
#define GEMMB_SMEM (3 * BB_STAGE * 2)

template <int EPI>
__global__ __launch_bounds__(256)
void gemm_bf_big(const __nv_bfloat16* __restrict__ A, int lda,
                 const __nv_bfloat16* __restrict__ W,
                 float* __restrict__ C,
                 int N, int K,
                 const float* __restrict__ res,
                 const float* __restrict__ ls) {
    extern __shared__ char smem_raw[];
    __nv_bfloat16* dyn = (__nv_bfloat16*)smem_raw;

    const int tid = threadIdx.x;
    const int warp = tid >> 5, lane = tid & 31;
    const int wm = (warp >> 2) * 64;
    const int wn = (warp & 3) * 32;
    const int m0 = blockIdx.y * 128, n0 = blockIdx.x * 128;
    const int lq = lane >> 2, lp = lane & 3;

    auto issue_tile = [&](int st, int k0) {
        __nv_bfloat16* As = dyn + st * BB_STAGE;
        __nv_bfloat16* Ws = As + BB_ABUF;
#pragma unroll
        for (int t = 0; t < 2; t++) {
            int fidx = tid + t * 256;
            int m = fidx >> 2, kc = fidx & 3;
            cp16(smem_u32(&As[m * BB_STR + kc * 8]),
                 &A[(size_t)(m0 + m) * lda + k0 + kc * 8]);
        }
#pragma unroll
        for (int t = 0; t < 2; t++) {
            int fidx = tid + t * 256;
            int n = fidx >> 2, kc = fidx & 3;
            cp16(smem_u32(&Ws[n * BB_STR + kc * 8]),
                 &W[(size_t)(n0 + n) * K + k0 + kc * 8]);
        }
        asm volatile("cp.async.commit_group;");
    };

    float acc[4][4][4];
#pragma unroll
    for (int i = 0; i < 4; i++)
#pragma unroll
        for (int j = 0; j < 4; j++)
#pragma unroll
            for (int q = 0; q < 4; q++) acc[i][j][q] = 0.f;

    const int nit = K / 32;
    issue_tile(0, 0);
    if (nit > 1) issue_tile(1, 32);

    for (int it = 0; it < nit; it++) {
        if (it + 1 < nit) asm volatile("cp.async.wait_group 1;");
        else              asm volatile("cp.async.wait_group 0;");
        __syncthreads();
        if (it + 2 < nit) issue_tile((it + 2) % 3, (it + 2) * 32);

        const __nv_bfloat16* ab = dyn + (it % 3) * BB_STAGE;
        const __nv_bfloat16* wb = ab + BB_ABUF;
#pragma unroll
        for (int kk = 0; kk < 2; kk++) {
            const int kb = kk * 16;
            unsigned int a[4][4], b[4][2];
#pragma unroll
            for (int mf = 0; mf < 4; mf++) {
                int r = wm + mf * 16 + lq;
                a[mf][0] = *(const unsigned*)&ab[r * BB_STR + kb + lp * 2];
                a[mf][1] = *(const unsigned*)&ab[(r + 8) * BB_STR + kb + lp * 2];
                a[mf][2] = *(const unsigned*)&ab[r * BB_STR + kb + 8 + lp * 2];
                a[mf][3] = *(const unsigned*)&ab[(r + 8) * BB_STR + kb + 8 + lp * 2];
            }
#pragma unroll
            for (int nf = 0; nf < 4; nf++) {
                int n = wn + nf * 8 + lq;
                b[nf][0] = *(const unsigned*)&wb[n * BB_STR + kb + lp * 2];
                b[nf][1] = *(const unsigned*)&wb[n * BB_STR + kb + 8 + lp * 2];
            }
#pragma unroll
            for (int mf = 0; mf < 4; mf++)
#pragma unroll
                for (int nf = 0; nf < 4; nf++) {
                    asm volatile(
                        "mma.sync.aligned.m16n8k16.row.col.f32.bf16.bf16.f32 "
                        "{%0,%1,%2,%3},{%4,%5,%6,%7},{%8,%9},{%0,%1,%2,%3};"
                        : "+f"(acc[mf][nf][0]), "+f"(acc[mf][nf][1]),
                          "+f"(acc[mf][nf][2]), "+f"(acc[mf][nf][3])
                        : "r"(a[mf][0]), "r"(a[mf][1]), "r"(a[mf][2]), "r"(a[mf][3]),
                          "r"(b[nf][0]), "r"(b[nf][1]));
                }
        }
        __syncthreads();
    }

#pragma unroll
    for (int mf = 0; mf < 4; mf++) {
#pragma unroll
        for (int nf = 0; nf < 4; nf++) {
            int r0 = m0 + wm + mf * 16 + lq;
            int c0 = n0 + wn + nf * 8 + lp * 2;
            float2 v0 = make_float2(acc[mf][nf][0], acc[mf][nf][1]);
            float2 v1 = make_float2(acc[mf][nf][2], acc[mf][nf][3]);
            if (EPI == 1) {
                float2 r0v = *(const float2*)&res[(size_t)r0 * N + c0];
                float2 r1v = *(const float2*)&res[(size_t)(r0 + 8) * N + c0];
                float l0 = ls[c0], l1 = ls[c0 + 1];
                v0.x = r0v.x + l0 * v0.x; v0.y = r0v.y + l1 * v0.y;
                v1.x = r1v.x + l0 * v1.x; v1.y = r1v.y + l1 * v1.y;
            }
            *(float2*)&C[(size_t)r0 * N + c0] = v0;
            *(float2*)&C[(size_t)(r0 + 8) * N + c0] = v1;
        }
    }
}

// ============ narrow bf16 GEMM (x_proj): 128x64x32, double-buffered =============
#define NB_ABUF (128 * BB_STR)
#define NB_WBUF (64 * BB_STR)
#define GEMMN_SMEM ((2 * NB_ABUF + 2 * NB_WBUF) * 2)

template <int NVALID>
__global__ __launch_bounds__(256)
void gemm_bf_narrow(const __nv_bfloat16* __restrict__ A, int lda,
                    const __nv_bfloat16* __restrict__ W,
                    float* __restrict__ C,
                    int N, int K) {
    extern __shared__ char smem_raw[];
    __nv_bfloat16* As = (__nv_bfloat16*)smem_raw;          // [2][128][40]
    __nv_bfloat16* Ws = As + 2 * NB_ABUF;                  // [2][64][40]

    const int tid = threadIdx.x;
    const int warp = tid >> 5, lane = tid & 31;
    const int wm = (warp >> 1) * 32;
    const int wn = (warp & 1) * 32;
    const int m0 = blockIdx.y * 128, n0 = blockIdx.x * 64;
    const int lq = lane >> 2, lp = lane & 3;

    // zero-pad invalid W rows once (cp.async never writes them)
    if (NVALID < 64) {
        for (int i = tid; i < 2 * NB_WBUF; i += 256) {
            int row = (i % NB_WBUF) / BB_STR;
            if (row >= NVALID) Ws[i] = __float2bfloat16(0.f);
        }
    }

    auto issue_tile = [&](int buf, int k0) {
#pragma unroll
        for (int t = 0; t < 2; t++) {
            int fidx = tid + t * 256;
            int m = fidx >> 2, kc = fidx & 3;
            cp16(smem_u32(&As[buf * NB_ABUF + m * BB_STR + kc * 8]),
                 &A[(size_t)(m0 + m) * lda + k0 + kc * 8]);
        }
        {
            int n = tid >> 2, kc = tid & 3;
            if (NVALID == 64 || n < NVALID)
                cp16(smem_u32(&Ws[buf * NB_WBUF + n * BB_STR + kc * 8]),
                     &W[(size_t)(n0 + n) * K + k0 + kc * 8]);
        }
        asm volatile("cp.async.commit_group;");
    };

    float acc[2][4][4];
#pragma unroll
    for (int i = 0; i < 2; i++)
#pragma unroll
        for (int j = 0; j < 4; j++)
#pragma unroll
            for (int q = 0; q < 4; q++) acc[i][j][q] = 0.f;

    const int nit = K / 32;
    issue_tile(0, 0);

    for (int it = 0; it < nit; it++) {
        int buf = it & 1;
        if (it + 1 < nit) {
            issue_tile(buf ^ 1, (it + 1) * 32);
            asm volatile("cp.async.wait_group 1;");
        } else {
            asm volatile("cp.async.wait_group 0;");
        }
        __syncthreads();

        const __nv_bfloat16* ab = As + buf * NB_ABUF;
        const __nv_bfloat16* wb = Ws + buf * NB_WBUF;
#pragma unroll
        for (int kk = 0; kk < 2; kk++) {
            const int kb = kk * 16;
            unsigned int a[2][4], b[4][2];
#pragma unroll
            for (int mf = 0; mf < 2; mf++) {
                int r = wm + mf * 16 + lq;
                a[mf][0] = *(const unsigned*)&ab[r * BB_STR + kb + lp * 2];
                a[mf][1] = *(const unsigned*)&ab[(r + 8) * BB_STR + kb + lp * 2];
                a[mf][2] = *(const unsigned*)&ab[r * BB_STR + kb + 8 + lp * 2];
                a[mf][3] = *(const unsigned*)&ab[(r + 8) * BB_STR + kb + 8 + lp * 2];
            }
#pragma unroll
            for (int nf = 0; nf < 4; nf++) {
                int n = wn + nf * 8 + lq;
                b[nf][0] = *(const unsigned*)&wb[n * BB_STR + kb + lp * 2];
                b[nf][1] = *(const unsigned*)&wb[n * BB_STR + kb + 8 + lp * 2];
            }
#pragma unroll
            for (int mf = 0; mf < 2; mf++)
#pragma unroll
                for (int nf = 0; nf < 4; nf++) {
                    asm volatile(
                        "mma.sync.aligned.m16n8k16.row.col.f32.bf16.bf16.f32 "
                        "{%0,%1,%2,%3},{%4,%5,%6,%7},{%8,%9},{%0,%1,%2,%3};"
                        : "+f"(acc[mf][nf][0]), "+f"(acc[mf][nf][1]),
                          "+f"(acc[mf][nf][2]), "+f"(acc[mf][nf][3])
                        : "r"(a[mf][0]), "r"(a[mf][1]), "r"(a[mf][2]), "r"(a[mf][3]),
                          "r"(b[nf][0]), "r"(b[nf][1]));
                }
        }
        __syncthreads();
    }

#pragma unroll
    for (int mf = 0; mf < 2; mf++) {
#pragma unroll
        for (int nf = 0; nf < 4; nf++) {
            int r0 = m0 + wm + mf * 16 + lq;
            int c0 = n0 + wn + nf * 8 + lp * 2;
            if (NVALID < 64 && c0 >= NVALID) continue;
            float2 v0 = make_float2(acc[mf][nf][0], acc[mf][nf][1]);
            float2 v1 = make_float2(acc[mf][nf][2], acc[mf][nf][3]);
            *(float2*)&C[(size_t)r0 * N + c0] = v0;
            *(float2*)&C[(size_t)(r0 + 8) * N + c0] = v1;
        }
    }
}

// ---------------- causal depthwise conv(4) + bias + SiLU ------------------------
__global__ void conv_silu_kernel(const float* __restrict__ cw,
                                 const float* __restrict__ cb) {
    int idx = blockIdx.x * blockDim.x + threadIdx.x;  // over NTOK*DI
    int d = idx & (DI - 1);
    int n = idx >> 9;         // token index (b*SEQ + l)
    int l = n & (SEQ - 1);
    float acc = cb[d];
    const float* w = cw + d * 4;
#pragma unroll
    for (int j = 0; j < 4; j++) {
        int ll = l - 3 + j;
        if (ll >= 0) acc = fmaf(w[j], g_xz[(size_t)(n - 3 + j) * (2 * DI) + d], acc);
    }
    float su = acc * sigmoidf_(acc);
    g_u[idx] = su;
    g_ubf[idx] = __float2bfloat16(su);
}

// ---------------- selective scan: shuffle-free two-phase reduction --------------
#define TCH 16
__global__ __launch_bounds__(256)
void scan_kernel(const float* __restrict__ A_log,
                 const float* __restrict__ Dp,
                 const float* __restrict__ dtw,   // [DI,16]
                 const float* __restrict__ dtb) { // [DI]
    __shared__ float sx[TCH * 48];
    __shared__ float su_[TCH][17], sz_[TCH][17], sdt_[TCH][17];
    __shared__ float sdtw[16][17];
    __shared__ float sp[8][TCH][33];

    int tid = threadIdx.x;
    int half = tid >> 4;
    int s = tid & 15;
    int w = tid >> 5;
    int lane = tid & 31;
    int b = blockIdx.x >> 5;
    int d0 = (blockIdx.x & 31) << 4;
    int d = d0 + half;

    int lt = tid >> 4, lj = tid & 15;

    sdtw[s][half] = dtw[(d0 + half) * 16 + s];
    float dtb_j = dtb[d0 + lj];

    float As = -__expf(A_log[d * DS + s]);
    float h = 0.f;
    size_t base = (size_t)b * SEQ;

    int t2 = lane & 15, ch2 = lane >> 4;
    int cB = w * 2 + ch2;
    float Dv2 = Dp[d0 + cB];

    float p_x0, p_x1, p_x2, p_u, p_z;
    {
        const float* xrow = g_xdbl + base * 48;
        p_x0 = xrow[tid]; p_x1 = xrow[tid + 256]; p_x2 = xrow[tid + 512];
        size_t n = base + lt;
        p_u = g_u[n * DI + d0 + lj];
        p_z = g_xz[n * (2 * DI) + DI + d0 + lj];
    }

    for (int l0 = 0; l0 < SEQ; l0 += TCH) {
        __syncthreads();
        sx[tid] = p_x0; sx[tid + 256] = p_x1; sx[tid + 512] = p_x2;
        su_[lt][lj] = p_u; sz_[lt][lj] = p_z;
        __syncthreads();

        {
            float v = dtb_j;
#pragma unroll
            for (int r = 0; r < 16; r++)
                v = fmaf(sx[lt * 48 + r], sdtw[r][lj], v);
            sdt_[lt][lj] = (v > 20.f) ? v : log1pf(__expf(v));
        }

        if (l0 + TCH < SEQ) {
            const float* xrow = g_xdbl + (base + l0 + TCH) * 48;
            p_x0 = xrow[tid]; p_x1 = xrow[tid + 256]; p_x2 = xrow[tid + 512];
            size_t n = base + l0 + TCH + lt;
            p_u = g_u[n * DI + d0 + lj];
            p_z = g_xz[n * (2 * DI) + DI + d0 + lj];
        }
        __syncthreads();

        // ---- phase 1: recurrence, p_t buffered ----
        float p[TCH];
#pragma unroll
        for (int t = 0; t < TCH; t++) {
            float r  = sdt_[t][half];
            float uu = su_[t][half];
            float dA = __expf(r * As);
            h = fmaf(dA, h, (r * uu) * sx[t * 48 + 16 + s]);
            p[t] = h * sx[t * 48 + 32 + s];
        }

        // ---- phase 2: warp-local transpose + sum over states ----
#pragma unroll
        for (int t = 0; t < TCH; t++) sp[w][t][lane] = p[t];
        __syncwarp();
        float acc = 0.f;
#pragma unroll
        for (int k = 0; k < 16; k++) acc += sp[w][t2][ch2 * 16 + k];

        float uu2 = su_[t2][cB];
        float zz  = sz_[t2][cB];
        g_ybf[(base + l0 + t2) * DI + d0 + cB] =
            __float2bfloat16((acc + uu2 * Dv2) * (zz * sigmoidf_(zz)));
    }
}

// ---------------- host orchestration --------------------------------------------
extern "C" void kernel_launch(void* const* d_in, const int* in_sizes, int n_in,
                              void* d_out, int out_size) {
    const float* x    = (const float*)d_in[0];
    const float* ln_g = (const float*)d_in[1];
    const float* ln_b = (const float*)d_in[2];
    const float* inw  = (const float*)d_in[3];   // [2,1024,256]
    const float* cw   = (const float*)d_in[4];   // [2,512,4]
    const float* cb   = (const float*)d_in[5];   // [2,512]
    const float* xpw  = (const float*)d_in[6];   // [2,48,512]
    const float* dtw  = (const float*)d_in[7];   // [2,512,16]
    const float* dtb  = (const float*)d_in[8];   // [2,512]
    const float* alog = (const float*)d_in[9];   // [2,512,16]
    const float* dp   = (const float*)d_in[10];  // [2,512]
    const float* ow   = (const float*)d_in[11];  // [2,256,512]
    const float* ls   = (const float*)d_in[12];  // [2,256]
    float* out = (float*)d_out;

    cudaFuncSetAttribute(gemm_bf_big<0>, cudaFuncAttributeMaxDynamicSharedMemorySize, GEMMB_SMEM);
    cudaFuncSetAttribute(gemm_bf_big<1>, cudaFuncAttributeMaxDynamicSharedMemorySize, GEMMB_SMEM);
    cudaFuncSetAttribute(gemm_bf_narrow<48>, cudaFuncAttributeMaxDynamicSharedMemorySize, GEMMN_SMEM);

    __nv_bfloat16 *p_lnbf, *p_ubf, *p_ybf, *p_wbf;
    float *p_xz, *p_u, *p_xdbl;
    cudaGetSymbolAddress((void**)&p_lnbf, g_lnbf);
    cudaGetSymbolAddress((void**)&p_xz,   g_xz);
    cudaGetSymbolAddress((void**)&p_u,    g_u);
    cudaGetSymbolAddress((void**)&p_ubf,  g_ubf);
    cudaGetSymbolAddress((void**)&p_xdbl, g_xdbl);
    cudaGetSymbolAddress((void**)&p_ybf,  g_ybf);
    cudaGetSymbolAddress((void**)&p_wbf,  g_wbf);

    // 0) weight conversion (both layers)
    convert_weights<<<(2 * W_LAYER + 255) / 256, 256>>>(inw, xpw, ow);

    for (int i = 0; i < 2; i++) {
        const float* xin = (i == 0) ? x : out;
        const __nv_bfloat16* wl = p_wbf + (size_t)i * W_LAYER;

        // 1) layernorm (-> bf16)
        ln_kernel<<<NTOK / 8, 256>>>(xin, ln_g + i * DM, ln_b + i * DM);

        // 2) in_proj: [N,256] x [1024,256]^T -> [N,1024]  (bf16 mma, 3-stage)
        gemm_bf_big<0><<<dim3((2 * DI) / 128, NTOK / 128), 256, GEMMB_SMEM>>>(
            p_lnbf, DM, wl, p_xz, 2 * DI, DM, nullptr, nullptr);

        // 3) causal conv4 + bias + SiLU on u-half (fp32 + bf16 outputs)
        conv_silu_kernel<<<(NTOK * DI) / 256, 256>>>(cw + i * DI * 4, cb + i * DI);

        // 4) x_proj: [N,512] x [48,512]^T -> [N,48]  (bf16 mma, N padded to 64)
        gemm_bf_narrow<48><<<dim3(1, NTOK / 128), 256, GEMMN_SMEM>>>(
            p_ubf, DI, wl + W_XP_OFF, p_xdbl, 48, DI);

        // 5) selective scan with fused dt_proj + D skip + z gating (-> bf16 y)
        scan_kernel<<<(BATCH * DI) / 16, 256>>>(
            alog + (size_t)i * DI * DS, dp + i * DI,
            dtw + (size_t)i * DI * 16, dtb + i * DI);

        // 6) out_proj fused with residual + layer_scale: out = xin + ls * (y @ ow^T)
        gemm_bf_big<1><<<dim3(DM / 128, NTOK / 128), 256, GEMMB_SMEM>>>(
            p_ybf, DI, wl + W_OW_OFF, out, DM, DI, xin, ls + i * DM);
    }
}